// round 9
// baseline (speedup 1.0000x reference)
#include <cuda_runtime.h>
#include <mma.h>
#include <math.h>

using namespace nvcuda;

#define BB 8
#define CC 256
#define NN 4096
#define MM 512
#define EE 16
#define NH 8
#define FFNH 2048
#define EPSV 1.1920929e-07f

// ------------- scratch (__device__ globals; no allocation allowed) ---------------
__device__ float g_G   [NN * 256];            // gelu hidden of pos MLP
__device__ float g_PE  [NN * MM];             // pos_enc G@W2 (NO bias)
__device__ float g_RINV[BB * NN];             // patch rmsnorm rsqrt
__device__ float g_Q   [128 * 512];           // q rows=(b,e)  (NO bq bias)
__device__ float g_MOLN[128 * 512];           // normalized mol (residual)
__device__ float g_TQ  [(size_t)BB * 128 * 768]; // [tq' (256) | masked 0.125(q+bq) (512)]
__device__ float g_S   [(size_t)BB * 128 * NN];       // scores/probs  16.8 MB
__device__ float g_PAP [(size_t)16 * BB * 128 * 256]; // pa partials   16.8 MB
__device__ float g_OPEP[8 * 8 * 128 * 64];    // p@(pe+bv+b2) partials
__device__ float g_ATT0[128 * 512];           // attention out (pre-proj)
__device__ float g_ATT [128 * 512];           // attended (post residual)
__device__ float g_H1  [128 * 2048];          // ffn hidden

__device__ __forceinline__ float geluf(float x) {
    return 0.5f * x * (1.0f + erff(x * 0.70710678118654752440f));
}

template <int NWARPS, bool DOMAX>
__device__ __forceinline__ float blk_red(float v, float* red) {
    #pragma unroll
    for (int o = 16; o; o >>= 1) {
        float t = __shfl_xor_sync(0xffffffffu, v, o);
        v = DOMAX ? fmaxf(v, t) : v + t;
    }
    if ((threadIdx.x & 31) == 0) red[threadIdx.x >> 5] = v;
    __syncthreads();
    if (threadIdx.x < 32) {
        float r = (threadIdx.x < NWARPS) ? red[threadIdx.x] : (DOMAX ? -1e30f : 0.0f);
        #pragma unroll
        for (int o = NWARPS >> 1; o; o >>= 1) {
            float t = __shfl_xor_sync(0xffffffffu, r, o);
            r = DOMAX ? fmaxf(r, t) : r + t;
        }
        if (threadIdx.x == 0) red[0] = r;
    }
    __syncthreads();
    float s = red[0];
    __syncthreads();
    return s;
}

// ---------------- K1a: G = gelu(coords @ W1 + b1) ---------------------------------
__global__ void k_gel(const float* __restrict__ w1, const float* __restrict__ b1) {
    int n = blockIdx.x, k = threadIdx.x;  // 256
    float cd = (float)(n >> 8)        * 0.0625f;
    float ch = (float)((n >> 4) & 15) * 0.0625f;
    float cw = (float)(n & 15)        * 0.0625f;
    g_G[n * 256 + k] = geluf(cd * w1[k] + ch * w1[256 + k] + cw * w1[512 + k] + b1[k]);
}

// ---------------- K1b: PE = G @ W2 (tf32 TC, NO bias) ------------------------------
__global__ void __launch_bounds__(256) k_peg_tc(const float* __restrict__ w2) {
    __shared__ __align__(16) float As[128][36];
    __shared__ __align__(16) float Bs[32][132];
    int m0 = blockIdx.x * 128, j0 = blockIdx.y * 128, t = threadIdx.x;
    int w = t >> 5, wm = w >> 2, wn = w & 3;
    wmma::fragment<wmma::accumulator, 16, 16, 8, float> c[4][2];
    #pragma unroll
    for (int mi = 0; mi < 4; mi++)
        #pragma unroll
        for (int ni = 0; ni < 2; ni++) wmma::fill_fragment(c[mi][ni], 0.0f);
    for (int c0 = 0; c0 < 256; c0 += 32) {
        #pragma unroll
        for (int r = 0; r < 4; r++) {
            int i = t + 256 * r, row = i >> 3, kq = i & 7;
            float4 v = *(const float4*)&g_G[(size_t)(m0 + row) * 256 + c0 + kq * 4];
            As[row][kq * 4 + 0] = wmma::__float_to_tf32(v.x);
            As[row][kq * 4 + 1] = wmma::__float_to_tf32(v.y);
            As[row][kq * 4 + 2] = wmma::__float_to_tf32(v.z);
            As[row][kq * 4 + 3] = wmma::__float_to_tf32(v.w);
        }
        #pragma unroll
        for (int r = 0; r < 4; r++) {
            int i = t + 256 * r, kk = i >> 5, nq = i & 31;
            float4 v = *(const float4*)&w2[(size_t)(c0 + kk) * 512 + j0 + nq * 4];
            Bs[kk][nq * 4 + 0] = wmma::__float_to_tf32(v.x);
            Bs[kk][nq * 4 + 1] = wmma::__float_to_tf32(v.y);
            Bs[kk][nq * 4 + 2] = wmma::__float_to_tf32(v.z);
            Bs[kk][nq * 4 + 3] = wmma::__float_to_tf32(v.w);
        }
        __syncthreads();
        #pragma unroll
        for (int kf = 0; kf < 4; kf++) {
            wmma::fragment<wmma::matrix_a, 16, 16, 8, wmma::precision::tf32, wmma::row_major> af[4];
            wmma::fragment<wmma::matrix_b, 16, 16, 8, wmma::precision::tf32, wmma::row_major> bf[2];
            #pragma unroll
            for (int mi = 0; mi < 4; mi++)
                wmma::load_matrix_sync(af[mi], &As[wm * 64 + mi * 16][kf * 8], 36);
            #pragma unroll
            for (int ni = 0; ni < 2; ni++)
                wmma::load_matrix_sync(bf[ni], &Bs[kf * 8][wn * 32 + ni * 16], 132);
            #pragma unroll
            for (int mi = 0; mi < 4; mi++)
                #pragma unroll
                for (int ni = 0; ni < 2; ni++)
                    wmma::mma_sync(c[mi][ni], af[mi], bf[ni], c[mi][ni]);
        }
        __syncthreads();
    }
    #pragma unroll
    for (int mi = 0; mi < 4; mi++)
        #pragma unroll
        for (int ni = 0; ni < 2; ni++)
            wmma::store_matrix_sync(&g_PE[(size_t)(m0 + wm * 64 + mi * 16) * 512 + j0 + wn * 32 + ni * 16],
                                    c[mi][ni], 512, wmma::mem_row_major);
}

// ---------------- K2: patch rmsnorm rsqrt factor ---------------------------------
__global__ void k_rinv(const float* __restrict__ X) {
    int t = blockIdx.x * blockDim.x + threadIdx.x;
    int b = t >> 12, n = t & (NN - 1);
    const float* p = X + (size_t)b * CC * NN + n;
    float s = 0.0f;
    #pragma unroll 8
    for (int c = 0; c < CC; c++) { float v = p[(size_t)c * NN]; s += v * v; }
    g_RINV[t] = rsqrtf(s * (1.0f / 256.0f) + EPSV);
}

// ---------------- K3: mol rmsnorm + Q = moln @ Wq (tf32 TC, NO bias) ---------------
// grid(4 jb), 256 thr, tile 128x128, K=512; also writes g_MOLN (block 0)
__global__ void __launch_bounds__(256) k_molq_tc(const float* __restrict__ mol,
                                                 const float* __restrict__ wmol,
                                                 const float* __restrict__ wq) {
    __shared__ __align__(16) float As[128][36];
    __shared__ __align__(16) float Bs[32][132];
    __shared__ float rinv_s[128];
    int jb = blockIdx.x * 128, t = threadIdx.x;
    int w = t >> 5, lane = t & 31;
    // rmsnorm factors: warp w handles rows w*16 .. w*16+15
    for (int i = 0; i < 16; i++) {
        int row = w * 16 + i;
        float ss = 0.f;
        #pragma unroll
        for (int q = 0; q < 16; q++) {
            float v = mol[row * 512 + lane + q * 32];
            ss += v * v;
        }
        #pragma unroll
        for (int o = 16; o; o >>= 1) ss += __shfl_xor_sync(0xffffffffu, ss, o);
        if (lane == 0) rinv_s[row] = rsqrtf(ss * (1.0f / 512.0f) + EPSV);
    }
    __syncthreads();
    if (blockIdx.x == 0) {
        for (int idx = t; idx < 16384; idx += 256) {
            int row = idx >> 7, j4 = (idx & 127) * 4;
            float4 m4 = *(const float4*)&mol[row * 512 + j4];
            float4 w4 = *(const float4*)&wmol[j4];
            float rv = rinv_s[row];
            float4 o = make_float4(m4.x * rv * w4.x, m4.y * rv * w4.y,
                                   m4.z * rv * w4.z, m4.w * rv * w4.w);
            *(float4*)&g_MOLN[row * 512 + j4] = o;
        }
    }
    int wm = w >> 2, wn = w & 3;
    wmma::fragment<wmma::accumulator, 16, 16, 8, float> c[4][2];
    #pragma unroll
    for (int mi = 0; mi < 4; mi++)
        #pragma unroll
        for (int ni = 0; ni < 2; ni++) wmma::fill_fragment(c[mi][ni], 0.0f);
    for (int c0 = 0; c0 < 512; c0 += 32) {
        #pragma unroll
        for (int r = 0; r < 4; r++) {
            int i = t + 256 * r, row = i >> 3, kq = i & 7;
            float4 m4 = *(const float4*)&mol[row * 512 + c0 + kq * 4];
            float4 w4 = *(const float4*)&wmol[c0 + kq * 4];
            float rv = rinv_s[row];
            As[row][kq * 4 + 0] = wmma::__float_to_tf32(m4.x * rv * w4.x);
            As[row][kq * 4 + 1] = wmma::__float_to_tf32(m4.y * rv * w4.y);
            As[row][kq * 4 + 2] = wmma::__float_to_tf32(m4.z * rv * w4.z);
            As[row][kq * 4 + 3] = wmma::__float_to_tf32(m4.w * rv * w4.w);
        }
        #pragma unroll
        for (int r = 0; r < 4; r++) {
            int i = t + 256 * r, kk = i >> 5, nq = i & 31;
            float4 v = *(const float4*)&wq[(size_t)(c0 + kk) * 512 + jb + nq * 4];
            Bs[kk][nq * 4 + 0] = wmma::__float_to_tf32(v.x);
            Bs[kk][nq * 4 + 1] = wmma::__float_to_tf32(v.y);
            Bs[kk][nq * 4 + 2] = wmma::__float_to_tf32(v.z);
            Bs[kk][nq * 4 + 3] = wmma::__float_to_tf32(v.w);
        }
        __syncthreads();
        #pragma unroll
        for (int kf = 0; kf < 4; kf++) {
            wmma::fragment<wmma::matrix_a, 16, 16, 8, wmma::precision::tf32, wmma::row_major> af[4];
            wmma::fragment<wmma::matrix_b, 16, 16, 8, wmma::precision::tf32, wmma::row_major> bf[2];
            #pragma unroll
            for (int mi = 0; mi < 4; mi++)
                wmma::load_matrix_sync(af[mi], &As[wm * 64 + mi * 16][kf * 8], 36);
            #pragma unroll
            for (int ni = 0; ni < 2; ni++)
                wmma::load_matrix_sync(bf[ni], &Bs[kf * 8][wn * 32 + ni * 16], 132);
            #pragma unroll
            for (int mi = 0; mi < 4; mi++)
                #pragma unroll
                for (int ni = 0; ni < 2; ni++)
                    wmma::mma_sync(c[mi][ni], af[mi], bf[ni], c[mi][ni]);
        }
        __syncthreads();
    }
    #pragma unroll
    for (int mi = 0; mi < 4; mi++)
        #pragma unroll
        for (int ni = 0; ni < 2; ni++)
            wmma::store_matrix_sync(&g_Q[(wm * 64 + mi * 16) * 512 + jb + wn * 32 + ni * 16],
                                    c[mi][ni], 512, wmma::mem_row_major);
}

// ---------------- K5: tq' cols 0..255 = 0.125*wp[c]*((q+bq)_h . Wk_h[c,:]) ---------
//                      cols 256..767 (cb==0) = head-masked 0.125*(q+bq)
__global__ void __launch_bounds__(256) k_tq2(const float* __restrict__ wkv,
                                             const float* __restrict__ wp,
                                             const float* __restrict__ bq) {
    __shared__ float As[16][128];
    __shared__ float Bs[16][128];
    __shared__ float bq_s[64];
    int h = blockIdx.x, c0b = blockIdx.y * 128, t = threadIdx.x;
    int tr = t >> 4, tc = t & 15;
    if (t < 16) *(float4*)&bq_s[t * 4] = *(const float4*)&bq[h * 64 + t * 4];
    __syncthreads();
    float acc[8][8];
    #pragma unroll
    for (int i = 0; i < 8; i++)
        #pragma unroll
        for (int j = 0; j < 8; j++) acc[i][j] = 0.f;
    for (int k0 = 0; k0 < 64; k0 += 16) {
        {
            int r = t >> 1, k8 = (t & 1) * 8;
            const float* src = &g_Q[r * 512 + h * 64 + k0 + k8];
            float4 a0 = *(const float4*)&src[0];
            float4 a1 = *(const float4*)&src[4];
            As[k8 + 0][r] = a0.x + bq_s[k0 + k8 + 0];
            As[k8 + 1][r] = a0.y + bq_s[k0 + k8 + 1];
            As[k8 + 2][r] = a0.z + bq_s[k0 + k8 + 2];
            As[k8 + 3][r] = a0.w + bq_s[k0 + k8 + 3];
            As[k8 + 4][r] = a1.x + bq_s[k0 + k8 + 4];
            As[k8 + 5][r] = a1.y + bq_s[k0 + k8 + 5];
            As[k8 + 6][r] = a1.z + bq_s[k0 + k8 + 6];
            As[k8 + 7][r] = a1.w + bq_s[k0 + k8 + 7];
        }
        {
            int c = t >> 1, k8 = (t & 1) * 8;
            const float* src = &wkv[(size_t)(c0b + c) * 1024 + h * 64 + k0 + k8];
            float4 v0 = *(const float4*)&src[0];
            float4 v1 = *(const float4*)&src[4];
            Bs[k8 + 0][c] = v0.x; Bs[k8 + 1][c] = v0.y; Bs[k8 + 2][c] = v0.z; Bs[k8 + 3][c] = v0.w;
            Bs[k8 + 4][c] = v1.x; Bs[k8 + 5][c] = v1.y; Bs[k8 + 6][c] = v1.z; Bs[k8 + 7][c] = v1.w;
        }
        __syncthreads();
        #pragma unroll
        for (int kk = 0; kk < 16; kk++) {
            float4 a0 = *(const float4*)&As[kk][tr * 8];
            float4 a1 = *(const float4*)&As[kk][tr * 8 + 4];
            float4 b0 = *(const float4*)&Bs[kk][tc * 8];
            float4 b1 = *(const float4*)&Bs[kk][tc * 8 + 4];
            float a[8] = {a0.x, a0.y, a0.z, a0.w, a1.x, a1.y, a1.z, a1.w};
            float bb[8] = {b0.x, b0.y, b0.z, b0.w, b1.x, b1.y, b1.z, b1.w};
            #pragma unroll
            for (int i = 0; i < 8; i++)
                #pragma unroll
                for (int j = 0; j < 8; j++) acc[i][j] += a[i] * bb[j];
        }
        __syncthreads();
    }
    float4 wp0 = *(const float4*)&wp[c0b + tc * 8];
    float4 wp1 = *(const float4*)&wp[c0b + tc * 8 + 4];
    float wpv[8] = {wp0.x, wp0.y, wp0.z, wp0.w, wp1.x, wp1.y, wp1.z, wp1.w};
    #pragma unroll
    for (int i = 0; i < 8; i++) {
        int r = tr * 8 + i, b = r >> 4, e = r & 15;
        float* dst = &g_TQ[((size_t)b * 128 + h * 16 + e) * 768 + c0b + tc * 8];
        #pragma unroll
        for (int j = 0; j < 8; j++) dst[j] = acc[i][j] * wpv[j] * 0.125f;
    }
    // masked 0.125*(q+bq) into cols 256..767 (one block per h: cb==0)
    if (blockIdx.y == 0) {
        for (int idx = t; idx < 128 * 128; idx += 256) {
            int r = idx >> 7, j4 = (idx & 127) * 4;
            int b = r >> 4, e = r & 15;
            float4 o = make_float4(0.f, 0.f, 0.f, 0.f);
            if ((j4 >> 6) == h) {
                float4 qv = *(const float4*)&g_Q[r * 512 + j4];
                int jo = j4 - h * 64;
                o.x = 0.125f * (qv.x + bq_s[jo + 0]);
                o.y = 0.125f * (qv.y + bq_s[jo + 1]);
                o.z = 0.125f * (qv.z + bq_s[jo + 2]);
                o.w = 0.125f * (qv.w + bq_s[jo + 3]);
            }
            *(float4*)&g_TQ[((size_t)b * 128 + h * 16 + e) * 768 + 256 + j4] = o;
        }
    }
}

// ---------------- K7: scores (tf32 TC): S = TQ768 @ [X*rinv ; PE^T+(bk+b2)] --------
// grid(32 nt, 8 b), 256 thr, tile 128x128, K=768
__global__ void __launch_bounds__(256) k_scores_tc(const float* __restrict__ X,
                                                   const float* __restrict__ bkv,
                                                   const float* __restrict__ peb2) {
    __shared__ __align__(16) float As[128][36];
    __shared__ __align__(16) float Bs[32][132];
    __shared__ __align__(16) float rs[128];
    __shared__ __align__(16) float cb_s[512];
    int n0 = blockIdx.x * 128, b = blockIdx.y, t = threadIdx.x;
    int w = t >> 5, wm = w >> 2, wn = w & 3;
    const float* Xb = X + (size_t)b * CC * NN;
    const float* TQ = g_TQ + (size_t)b * 128 * 768;
    float* Sb = g_S + (size_t)b * 128 * 4096;
    if (t < 32) *(float4*)&rs[t * 4] = *(const float4*)&g_RINV[b * 4096 + n0 + t * 4];
    if (t >= 128 && t < 256) {
        int i = t - 128;
        float4 bk4 = *(const float4*)&bkv[i * 4];
        float4 b24 = *(const float4*)&peb2[i * 4];
        cb_s[i * 4 + 0] = bk4.x + b24.x;
        cb_s[i * 4 + 1] = bk4.y + b24.y;
        cb_s[i * 4 + 2] = bk4.z + b24.z;
        cb_s[i * 4 + 3] = bk4.w + b24.w;
    }
    __syncthreads();
    wmma::fragment<wmma::accumulator, 16, 16, 8, float> c[4][2];
    #pragma unroll
    for (int mi = 0; mi < 4; mi++)
        #pragma unroll
        for (int ni = 0; ni < 2; ni++) wmma::fill_fragment(c[mi][ni], 0.0f);
    for (int c0 = 0; c0 < 768; c0 += 32) {
        #pragma unroll
        for (int r = 0; r < 4; r++) {
            int i = t + 256 * r, row = i >> 3, kq = i & 7;
            float4 v = *(const float4*)&TQ[(size_t)row * 768 + c0 + kq * 4];
            As[row][kq * 4 + 0] = wmma::__float_to_tf32(v.x);
            As[row][kq * 4 + 1] = wmma::__float_to_tf32(v.y);
            As[row][kq * 4 + 2] = wmma::__float_to_tf32(v.z);
            As[row][kq * 4 + 3] = wmma::__float_to_tf32(v.w);
        }
        if (c0 < 256) {
            #pragma unroll
            for (int r = 0; r < 4; r++) {
                int i = t + 256 * r, kk = i >> 5, nq = i & 31;
                float4 v = *(const float4*)&Xb[(size_t)(c0 + kk) * 4096 + n0 + nq * 4];
                Bs[kk][nq * 4 + 0] = wmma::__float_to_tf32(v.x * rs[nq * 4 + 0]);
                Bs[kk][nq * 4 + 1] = wmma::__float_to_tf32(v.y * rs[nq * 4 + 1]);
                Bs[kk][nq * 4 + 2] = wmma::__float_to_tf32(v.z * rs[nq * 4 + 2]);
                Bs[kk][nq * 4 + 3] = wmma::__float_to_tf32(v.w * rs[nq * 4 + 3]);
            }
        } else {
            int jb = c0 - 256;
            #pragma unroll
            for (int r = 0; r < 4; r++) {
                int i = t + 256 * r, n = i >> 3, jq = i & 7;
                float4 v = *(const float4*)&g_PE[(size_t)(n0 + n) * 512 + jb + jq * 4];
                int j = jb + jq * 4;
                Bs[jq * 4 + 0][n] = wmma::__float_to_tf32(v.x + cb_s[j + 0]);
                Bs[jq * 4 + 1][n] = wmma::__float_to_tf32(v.y + cb_s[j + 1]);
                Bs[jq * 4 + 2][n] = wmma::__float_to_tf32(v.z + cb_s[j + 2]);
                Bs[jq * 4 + 3][n] = wmma::__float_to_tf32(v.w + cb_s[j + 3]);
            }
        }
        __syncthreads();
        #pragma unroll
        for (int kf = 0; kf < 4; kf++) {
            wmma::fragment<wmma::matrix_a, 16, 16, 8, wmma::precision::tf32, wmma::row_major> af[4];
            wmma::fragment<wmma::matrix_b, 16, 16, 8, wmma::precision::tf32, wmma::row_major> bf[2];
            #pragma unroll
            for (int mi = 0; mi < 4; mi++)
                wmma::load_matrix_sync(af[mi], &As[wm * 64 + mi * 16][kf * 8], 36);
            #pragma unroll
            for (int ni = 0; ni < 2; ni++)
                wmma::load_matrix_sync(bf[ni], &Bs[kf * 8][wn * 32 + ni * 16], 132);
            #pragma unroll
            for (int mi = 0; mi < 4; mi++)
                #pragma unroll
                for (int ni = 0; ni < 2; ni++)
                    wmma::mma_sync(c[mi][ni], af[mi], bf[ni], c[mi][ni]);
        }
        __syncthreads();
    }
    #pragma unroll
    for (int mi = 0; mi < 4; mi++)
        #pragma unroll
        for (int ni = 0; ni < 2; ni++)
            wmma::store_matrix_sync(&Sb[(size_t)(wm * 64 + mi * 16) * 4096 + n0 + wn * 32 + ni * 16],
                                    c[mi][ni], 4096, wmma::mem_row_major);
}

// ---------------- K8: softmax over n=4096 ------------------------------------------
__global__ void k_softmax() {
    __shared__ float red[32];
    int row = blockIdx.x;
    float* s = g_S + (size_t)row * NN;
    int t = threadIdx.x;  // 256
    float loc[16];
    float m = -1e30f;
    #pragma unroll
    for (int i = 0; i < 16; i++) { loc[i] = s[t + i * 256]; m = fmaxf(m, loc[i]); }
    m = blk_red<8, true>(m, red);
    float sum = 0.0f;
    #pragma unroll
    for (int i = 0; i < 16; i++) { loc[i] = expf(loc[i] - m); sum += loc[i]; }
    sum = blk_red<8, false>(sum, red);
    float inv = 1.0f / sum;
    #pragma unroll
    for (int i = 0; i < 16; i++) s[t + i * 256] = loc[i] * inv;
}

// ---------------- K9: pa partials (tf32 TC): (p*rinv) @ X^T ------------------------
__global__ void __launch_bounds__(512) k_pa_tc(const float* __restrict__ X) {
    __shared__ __align__(16) float As[128][20];
    __shared__ __align__(16) float Bs[256][20];
    int ks = blockIdx.x, b = blockIdx.y, t = threadIdx.x;
    int nbase = ks * 256;
    int w = t >> 5, wm = w >> 3, wn = w & 7;
    const float* Xb = X + (size_t)b * CC * NN;
    wmma::fragment<wmma::accumulator, 16, 16, 8, float> c[4][2];
    #pragma unroll
    for (int mi = 0; mi < 4; mi++)
        #pragma unroll
        for (int ni = 0; ni < 2; ni++) wmma::fill_fragment(c[mi][ni], 0.0f);
    for (int k0 = 0; k0 < 256; k0 += 16) {
        {
            int row = t >> 2, kq = t & 3;
            int n = nbase + k0 + kq * 4;
            float4 p  = *(const float4*)&g_S[(size_t)(b * 128 + row) * 4096 + n];
            float4 rv = *(const float4*)&g_RINV[b * 4096 + n];
            As[row][kq * 4 + 0] = wmma::__float_to_tf32(p.x * rv.x);
            As[row][kq * 4 + 1] = wmma::__float_to_tf32(p.y * rv.y);
            As[row][kq * 4 + 2] = wmma::__float_to_tf32(p.z * rv.z);
            As[row][kq * 4 + 3] = wmma::__float_to_tf32(p.w * rv.w);
        }
        #pragma unroll
        for (int r = 0; r < 2; r++) {
            int i = t + 512 * r, cc = i >> 2, kq = i & 3;
            float4 v = *(const float4*)&Xb[(size_t)cc * 4096 + nbase + k0 + kq * 4];
            Bs[cc][kq * 4 + 0] = wmma::__float_to_tf32(v.x);
            Bs[cc][kq * 4 + 1] = wmma::__float_to_tf32(v.y);
            Bs[cc][kq * 4 + 2] = wmma::__float_to_tf32(v.z);
            Bs[cc][kq * 4 + 3] = wmma::__float_to_tf32(v.w);
        }
        __syncthreads();
        #pragma unroll
        for (int kf = 0; kf < 2; kf++) {
            wmma::fragment<wmma::matrix_a, 16, 16, 8, wmma::precision::tf32, wmma::row_major> af[4];
            wmma::fragment<wmma::matrix_b, 16, 16, 8, wmma::precision::tf32, wmma::col_major> bf[2];
            #pragma unroll
            for (int mi = 0; mi < 4; mi++)
                wmma::load_matrix_sync(af[mi], &As[wm * 64 + mi * 16][kf * 8], 20);
            #pragma unroll
            for (int ni = 0; ni < 2; ni++)
                wmma::load_matrix_sync(bf[ni], &Bs[wn * 32 + ni * 16][kf * 8], 20);
            #pragma unroll
            for (int mi = 0; mi < 4; mi++)
                #pragma unroll
                for (int ni = 0; ni < 2; ni++)
                    wmma::mma_sync(c[mi][ni], af[mi], bf[ni], c[mi][ni]);
        }
        __syncthreads();
    }
    #pragma unroll
    for (int mi = 0; mi < 4; mi++)
        #pragma unroll
        for (int ni = 0; ni < 2; ni++)
            wmma::store_matrix_sync(
                &g_PAP[(size_t)((ks * 8 + b) * 128 + wm * 64 + mi * 16) * 256 + wn * 32 + ni * 16],
                c[mi][ni], 256, wmma::mem_row_major);
}

// ---------------- K10: ope partials (tf32 TC): p @ (PE_h + bv + b2) ----------------
// grid(8 h, 8 ks), 256 thr (4m x 2n warps), tile 128x64, Kchunk=512 (inner 32)
__global__ void __launch_bounds__(256) k_ppe_tc(const float* __restrict__ bkv,
                                                const float* __restrict__ peb2) {
    __shared__ __align__(16) float As[128][36];
    __shared__ __align__(16) float Bs[32][68];
    __shared__ float bias_s[64];
    int h = blockIdx.x, ks = blockIdx.y, t = threadIdx.x;
    int nb = ks * 512;
    int w = t >> 5, wm = w >> 1, wn = w & 1;
    if (t < 16) {
        float4 bv4 = *(const float4*)&bkv[512 + h * 64 + t * 4];
        float4 b24 = *(const float4*)&peb2[h * 64 + t * 4];
        bias_s[t * 4 + 0] = bv4.x + b24.x;
        bias_s[t * 4 + 1] = bv4.y + b24.y;
        bias_s[t * 4 + 2] = bv4.z + b24.z;
        bias_s[t * 4 + 3] = bv4.w + b24.w;
    }
    __syncthreads();
    wmma::fragment<wmma::accumulator, 16, 16, 8, float> c[2][2];
    #pragma unroll
    for (int mi = 0; mi < 2; mi++)
        #pragma unroll
        for (int ni = 0; ni < 2; ni++) wmma::fill_fragment(c[mi][ni], 0.0f);
    for (int k0 = 0; k0 < 512; k0 += 32) {
        #pragma unroll
        for (int r = 0; r < 4; r++) {
            int i = t + 256 * r, row = i >> 3, kq = i & 7;
            int b = row >> 4, e = row & 15;
            float4 v = *(const float4*)&g_S[(size_t)((b * 8 + h) * 16 + e) * 4096 + nb + k0 + kq * 4];
            As[row][kq * 4 + 0] = wmma::__float_to_tf32(v.x);
            As[row][kq * 4 + 1] = wmma::__float_to_tf32(v.y);
            As[row][kq * 4 + 2] = wmma::__float_to_tf32(v.z);
            As[row][kq * 4 + 3] = wmma::__float_to_tf32(v.w);
        }
        #pragma unroll
        for (int r = 0; r < 2; r++) {
            int i = t + 256 * r, kk = i >> 4, dq = i & 15;
            float4 v = *(const float4*)&g_PE[(size_t)(nb + k0 + kk) * 512 + h * 64 + dq * 4];
            Bs[kk][dq * 4 + 0] = wmma::__float_to_tf32(v.x + bias_s[dq * 4 + 0]);
            Bs[kk][dq * 4 + 1] = wmma::__float_to_tf32(v.y + bias_s[dq * 4 + 1]);
            Bs[kk][dq * 4 + 2] = wmma::__float_to_tf32(v.z + bias_s[dq * 4 + 2]);
            Bs[kk][dq * 4 + 3] = wmma::__float_to_tf32(v.w + bias_s[dq * 4 + 3]);
        }
        __syncthreads();
        #pragma unroll
        for (int kf = 0; kf < 4; kf++) {
            wmma::fragment<wmma::matrix_a, 16, 16, 8, wmma::precision::tf32, wmma::row_major> af[2];
            wmma::fragment<wmma::matrix_b, 16, 16, 8, wmma::precision::tf32, wmma::row_major> bf[2];
            #pragma unroll
            for (int mi = 0; mi < 2; mi++)
                wmma::load_matrix_sync(af[mi], &As[wm * 32 + mi * 16][kf * 8], 36);
            #pragma unroll
            for (int ni = 0; ni < 2; ni++)
                wmma::load_matrix_sync(bf[ni], &Bs[kf * 8][wn * 32 + ni * 16], 68);
            #pragma unroll
            for (int mi = 0; mi < 2; mi++)
                #pragma unroll
                for (int ni = 0; ni < 2; ni++)
                    wmma::mma_sync(c[mi][ni], af[mi], bf[ni], c[mi][ni]);
        }
        __syncthreads();
    }
    #pragma unroll
    for (int mi = 0; mi < 2; mi++)
        #pragma unroll
        for (int ni = 0; ni < 2; ni++)
            wmma::store_matrix_sync(
                &g_OPEP[(size_t)((ks * 8 + h) * 128 + wm * 32 + mi * 16) * 64 + wn * 32 + ni * 16],
                c[mi][ni], 64, wmma::mem_row_major);
}

// ---------------- K11: out0 = (pa*wp-reduced) @ Wv + ope (bias already in ope) -----
__global__ void __launch_bounds__(512) k_out(const float* __restrict__ wkv,
                                             const float* __restrict__ wp) {
    __shared__ float pool[8192];
    __shared__ float ope_s[4][512];
    int row0 = blockIdx.x * 4;
    int t = threadIdx.x;
    for (int idx = t; idx < 8192; idx += 512) {
        int r = idx >> 11, rest = idx & 2047, h = rest >> 8, c = rest & 255;
        int row = row0 + r, b = row >> 4, e = row & 15;
        float s = 0.f;
        #pragma unroll
        for (int ks = 0; ks < 16; ks++)
            s += g_PAP[(size_t)((ks * 8 + b) * 128 + h * 16 + e) * 256 + c];
        pool[idx] = s * wp[c];
    }
    for (int idx = t; idx < 2048; idx += 512) {
        int r = idx >> 9, j = idx & 511;
        int row = row0 + r, b = row >> 4, e = row & 15;
        int h = j >> 6, d = j & 63;
        float s = 0.f;
        #pragma unroll
        for (int ks = 0; ks < 8; ks++)
            s += g_OPEP[(size_t)((ks * 8 + h) * 128 + b * 16 + e) * 64 + d];
        ope_s[r][j] = s;
    }
    __syncthreads();
    int tj = t & 127, tk = t >> 7;
    int h = tj >> 4;
    float4 acc[4];
    #pragma unroll
    for (int r = 0; r < 4; r++) acc[r] = make_float4(0.f, 0.f, 0.f, 0.f);
    #pragma unroll 4
    for (int c = tk * 64; c < tk * 64 + 64; c++) {
        float4 w4 = *(const float4*)&wkv[(size_t)c * 1024 + 512 + tj * 4];
        #pragma unroll
        for (int r = 0; r < 4; r++) {
            float p = pool[r * 2048 + h * 256 + c];
            acc[r].x += p * w4.x; acc[r].y += p * w4.y;
            acc[r].z += p * w4.z; acc[r].w += p * w4.w;
        }
    }
    __syncthreads();
    #pragma unroll
    for (int r = 0; r < 4; r++) *(float4*)&pool[(tk * 4 + r) * 512 + tj * 4] = acc[r];
    __syncthreads();
    {
        int r = t >> 7, j0 = (t & 127) * 4;
        float4 s = make_float4(0.f, 0.f, 0.f, 0.f);
        #pragma unroll
        for (int k2 = 0; k2 < 4; k2++) {
            float4 p = *(const float4*)&pool[(k2 * 4 + r) * 512 + j0];
            s.x += p.x; s.y += p.y; s.z += p.z; s.w += p.w;
        }
        float4 op = *(const float4*)&ope_s[r][j0];
        s.x += op.x; s.y += op.y; s.z += op.z; s.w += op.w;
        *(float4*)&g_ATT0[(row0 + r) * 512 + j0] = s;
    }
}

// ---------------- K12: proj + residual ---------------------------------------------
__global__ void __launch_bounds__(256) k_proj(const float* __restrict__ wproj,
                                              const float* __restrict__ bproj) {
    __shared__ float x_s[8][512];
    __shared__ float part[8][8][128];
    int row0 = blockIdx.x * 8, jb = blockIdx.y * 128, t = threadIdx.x;
    for (int idx = t; idx < 4096; idx += 256)
        x_s[idx >> 9][idx & 511] = g_ATT0[(row0 + (idx >> 9)) * 512 + (idx & 511)];
    __syncthreads();
    int tk = t >> 5, tj = t & 31, j = jb + tj * 4;
    float4 acc[8];
    #pragma unroll
    for (int r = 0; r < 8; r++) acc[r] = make_float4(0.f, 0.f, 0.f, 0.f);
    #pragma unroll 4
    for (int c = tk * 64; c < tk * 64 + 64; c++) {
        float4 w4 = *(const float4*)&wproj[(size_t)c * 512 + j];
        #pragma unroll
        for (int r = 0; r < 8; r++) {
            float x = x_s[r][c];
            acc[r].x += x * w4.x; acc[r].y += x * w4.y;
            acc[r].z += x * w4.z; acc[r].w += x * w4.w;
        }
    }
    #pragma unroll
    for (int r = 0; r < 8; r++) *(float4*)&part[tk][r][tj * 4] = acc[r];
    __syncthreads();
    {
        int r = t >> 5, cq = t & 31, j2 = jb + cq * 4;
        float4 s = make_float4(0.f, 0.f, 0.f, 0.f);
        #pragma unroll
        for (int k2 = 0; k2 < 8; k2++) {
            float4 p = *(const float4*)&part[k2][r][cq * 4];
            s.x += p.x; s.y += p.y; s.z += p.z; s.w += p.w;
        }
        float4 bp = *(const float4*)&bproj[j2];
        float4 mn = *(const float4*)&g_MOLN[(row0 + r) * 512 + j2];
        s.x += bp.x + mn.x; s.y += bp.y + mn.y;
        s.z += bp.z + mn.z; s.w += bp.w + mn.w;
        *(float4*)&g_ATT[(row0 + r) * 512 + j2] = s;
    }
}

// ---------------- K13: ffn1 (fused rmsnorm) + gelu ----------------------------------
__global__ void __launch_bounds__(256) k_ffn1(const float* __restrict__ nw,
                                              const float* __restrict__ w1,
                                              const float* __restrict__ b1) {
    __shared__ float x_s[8][512];
    __shared__ float part[8][8][128];
    int row0 = blockIdx.x * 8, jb = blockIdx.y * 128, t = threadIdx.x;
    int w = t >> 5, lane = t & 31;
    {
        float vals[16]; float ss = 0.f;
        #pragma unroll
        for (int i = 0; i < 16; i++) {
            float v = g_ATT[(row0 + w) * 512 + lane + i * 32];
            vals[i] = v; ss += v * v;
        }
        #pragma unroll
        for (int o = 16; o; o >>= 1) ss += __shfl_xor_sync(0xffffffffu, ss, o);
        float rv = rsqrtf(ss * (1.0f / 512.0f) + EPSV);
        #pragma unroll
        for (int i = 0; i < 16; i++) {
            int m = lane + i * 32;
            x_s[w][m] = vals[i] * rv * nw[m];
        }
    }
    __syncthreads();
    int tk = t >> 5, tj = t & 31, j = jb + tj * 4;
    float4 acc[8];
    #pragma unroll
    for (int r = 0; r < 8; r++) acc[r] = make_float4(0.f, 0.f, 0.f, 0.f);
    #pragma unroll 4
    for (int c = tk * 64; c < tk * 64 + 64; c++) {
        float4 w4 = *(const float4*)&w1[(size_t)c * 2048 + j];
        #pragma unroll
        for (int r = 0; r < 8; r++) {
            float x = x_s[r][c];
            acc[r].x += x * w4.x; acc[r].y += x * w4.y;
            acc[r].z += x * w4.z; acc[r].w += x * w4.w;
        }
    }
    #pragma unroll
    for (int r = 0; r < 8; r++) *(float4*)&part[tk][r][tj * 4] = acc[r];
    __syncthreads();
    {
        int r = t >> 5, cq = t & 31, j2 = jb + cq * 4;
        float4 s = make_float4(0.f, 0.f, 0.f, 0.f);
        #pragma unroll
        for (int k2 = 0; k2 < 8; k2++) {
            float4 p = *(const float4*)&part[k2][r][cq * 4];
            s.x += p.x; s.y += p.y; s.z += p.z; s.w += p.w;
        }
        float4 bb = *(const float4*)&b1[j2];
        float4 o;
        o.x = geluf(s.x + bb.x); o.y = geluf(s.y + bb.y);
        o.z = geluf(s.z + bb.z); o.w = geluf(s.w + bb.w);
        *(float4*)&g_H1[(size_t)(row0 + r) * 2048 + j2] = o;
    }
}

// ---------------- K14: ffn2 + residual ----------------------------------------------
__global__ void __launch_bounds__(512) k_ffn2(const float* __restrict__ w2,
                                              const float* __restrict__ b2,
                                              float* __restrict__ out) {
    __shared__ float pool[8192];
    int row0 = blockIdx.x * 4, jb = blockIdx.y * 128, t = threadIdx.x;
    for (int idx = t; idx < 8192; idx += 512)
        pool[idx] = g_H1[(size_t)(row0 + (idx >> 11)) * 2048 + (idx & 2047)];
    __syncthreads();
    int tk = t >> 5, tj = t & 31, j = jb + tj * 4;
    float4 acc[4];
    #pragma unroll
    for (int r = 0; r < 4; r++) acc[r] = make_float4(0.f, 0.f, 0.f, 0.f);
    #pragma unroll 4
    for (int c = tk * 128; c < tk * 128 + 128; c++) {
        float4 w4 = *(const float4*)&w2[(size_t)c * 512 + j];
        #pragma unroll
        for (int r = 0; r < 4; r++) {
            float x = pool[r * 2048 + c];
            acc[r].x += x * w4.x; acc[r].y += x * w4.y;
            acc[r].z += x * w4.z; acc[r].w += x * w4.w;
        }
    }
    __syncthreads();
    #pragma unroll
    for (int r = 0; r < 4; r++) *(float4*)&pool[tk * 512 + r * 128 + tj * 4] = acc[r];
    __syncthreads();
    {
        int r = t >> 7, cq = t & 127;
        float s = 0.f;
        #pragma unroll
        for (int k2 = 0; k2 < 16; k2++) s += pool[k2 * 512 + r * 128 + cq];
        int j2 = jb + cq;
        out[(row0 + r) * 512 + j2] = s + b2[j2] + g_ATT[(row0 + r) * 512 + j2];
    }
}

// ---------------- launch -------------------------------------------------------------
extern "C" void kernel_launch(void* const* d_in, const int* in_sizes, int n_in,
                              void* d_out, int out_size) {
    const float* patch   = (const float*)d_in[0];
    const float* mol     = (const float*)d_in[1];
    const float* pe_w1   = (const float*)d_in[2];
    const float* pe_b1   = (const float*)d_in[3];
    const float* pe_w2   = (const float*)d_in[4];
    const float* pe_b2   = (const float*)d_in[5];
    const float* wq      = (const float*)d_in[6];
    const float* bq      = (const float*)d_in[7];
    const float* wkv     = (const float*)d_in[8];
    const float* bkv     = (const float*)d_in[9];
    const float* wproj   = (const float*)d_in[10];
    const float* bproj   = (const float*)d_in[11];
    const float* nmolw   = (const float*)d_in[12];
    const float* npatchw = (const float*)d_in[13];
    const float* ffn_w1  = (const float*)d_in[14];
    const float* ffn_b1  = (const float*)d_in[15];
    const float* ffn_w2  = (const float*)d_in[16];
    const float* ffn_b2  = (const float*)d_in[17];
    const float* ffn_nw  = (const float*)d_in[18];
    float* out = (float*)d_out;
    (void)in_sizes; (void)n_in; (void)out_size;

    k_gel      <<<NN, 256>>>(pe_w1, pe_b1);
    k_peg_tc   <<<dim3(32, 4), 256>>>(pe_w2);
    k_rinv     <<<(BB * NN) / 256, 256>>>(patch);
    k_molq_tc  <<<4, 256>>>(mol, nmolw, wq);
    k_tq2      <<<dim3(8, 2), 256>>>(wkv, npatchw, bq);
    k_scores_tc<<<dim3(32, 8), 256>>>(patch, bkv, pe_b2);
    k_softmax  <<<BB * 128, 256>>>();
    k_pa_tc    <<<dim3(16, 8), 512>>>(patch);
    k_ppe_tc   <<<dim3(8, 8), 256>>>(bkv, pe_b2);
    k_out      <<<32, 512>>>(wkv, npatchw);
    k_proj     <<<dim3(16, 4), 256>>>(wproj, bproj);
    k_ffn1     <<<dim3(16, 16), 256>>>(ffn_nw, ffn_w1, ffn_b1);
    k_ffn2     <<<dim3(32, 4), 512>>>(ffn_w2, ffn_b2, out);
}

// round 10
// speedup vs baseline: 1.3691x; 1.3691x over previous
#include <cuda_runtime.h>
#include <mma.h>
#include <math.h>

using namespace nvcuda;

#define BB 8
#define CC 256
#define NN 4096
#define MM 512
#define EE 16
#define NH 8
#define FFNH 2048
#define EPSV 1.1920929e-07f

// ------------- scratch (__device__ globals; no allocation allowed) ---------------
__device__ float g_G   [NN * 256];            // gelu hidden of pos MLP
__device__ float g_PE  [NN * MM];             // pos_enc G@W2 (NO bias)
__device__ float g_RINV[BB * NN];             // patch rmsnorm rsqrt
__device__ float g_Q   [128 * 512];           // q rows=(b,e) (includes bq)
__device__ float g_MOLN[128 * 512];           // normalized mol (residual)
__device__ float g_TQ  [BB * 128 * 256];      // tq' rows=(b, h*16+e), wp & 0.125 folded
__device__ float g_QBK [BB * NH * EE];        // q . (bk + b2)  (per b,h,e)
__device__ float g_S   [(size_t)BB * 128 * NN];       // scores/probs  16.8 MB
__device__ float g_PAP [(size_t)16 * BB * 128 * 256]; // pa partials   16.8 MB
__device__ float g_OPEP[8 * 8 * 128 * 64];    // p@(pe+bv+b2) partials
__device__ float g_ATT0[128 * 512];           // attention out (pre-proj)
__device__ float g_ATT [128 * 512];           // attended (post residual)
__device__ float g_H1  [128 * 2048];          // ffn hidden

__device__ __forceinline__ float geluf(float x) {
    return 0.5f * x * (1.0f + erff(x * 0.70710678118654752440f));
}

template <int NWARPS, bool DOMAX>
__device__ __forceinline__ float blk_red(float v, float* red) {
    #pragma unroll
    for (int o = 16; o; o >>= 1) {
        float t = __shfl_xor_sync(0xffffffffu, v, o);
        v = DOMAX ? fmaxf(v, t) : v + t;
    }
    if ((threadIdx.x & 31) == 0) red[threadIdx.x >> 5] = v;
    __syncthreads();
    if (threadIdx.x < 32) {
        float r = (threadIdx.x < NWARPS) ? red[threadIdx.x] : (DOMAX ? -1e30f : 0.0f);
        #pragma unroll
        for (int o = NWARPS >> 1; o; o >>= 1) {
            float t = __shfl_xor_sync(0xffffffffu, r, o);
            r = DOMAX ? fmaxf(r, t) : r + t;
        }
        if (threadIdx.x == 0) red[0] = r;
    }
    __syncthreads();
    float s = red[0];
    __syncthreads();
    return s;
}

// ---------------- K1a: G = gelu(coords @ W1 + b1) ---------------------------------
__global__ void k_gel(const float* __restrict__ w1, const float* __restrict__ b1) {
    int n = blockIdx.x, k = threadIdx.x;  // 256
    float cd = (float)(n >> 8)        * 0.0625f;
    float ch = (float)((n >> 4) & 15) * 0.0625f;
    float cw = (float)(n & 15)        * 0.0625f;
    g_G[n * 256 + k] = geluf(cd * w1[k] + ch * w1[256 + k] + cw * w1[512 + k] + b1[k]);
}

// ---------------- K1b: PE = G @ W2 (tf32 TC, NO bias) ------------------------------
__global__ void __launch_bounds__(256) k_peg_tc(const float* __restrict__ w2) {
    __shared__ __align__(16) float As[128][36];
    __shared__ __align__(16) float Bs[32][132];
    int m0 = blockIdx.x * 128, j0 = blockIdx.y * 128, t = threadIdx.x;
    int w = t >> 5, wm = w >> 2, wn = w & 3;
    wmma::fragment<wmma::accumulator, 16, 16, 8, float> c[4][2];
    #pragma unroll
    for (int mi = 0; mi < 4; mi++)
        #pragma unroll
        for (int ni = 0; ni < 2; ni++) wmma::fill_fragment(c[mi][ni], 0.0f);
    for (int c0 = 0; c0 < 256; c0 += 32) {
        #pragma unroll
        for (int r = 0; r < 4; r++) {
            int i = t + 256 * r, row = i >> 3, kq = i & 7;
            float4 v = *(const float4*)&g_G[(size_t)(m0 + row) * 256 + c0 + kq * 4];
            As[row][kq * 4 + 0] = wmma::__float_to_tf32(v.x);
            As[row][kq * 4 + 1] = wmma::__float_to_tf32(v.y);
            As[row][kq * 4 + 2] = wmma::__float_to_tf32(v.z);
            As[row][kq * 4 + 3] = wmma::__float_to_tf32(v.w);
        }
        #pragma unroll
        for (int r = 0; r < 4; r++) {
            int i = t + 256 * r, kk = i >> 5, nq = i & 31;
            float4 v = *(const float4*)&w2[(size_t)(c0 + kk) * 512 + j0 + nq * 4];
            Bs[kk][nq * 4 + 0] = wmma::__float_to_tf32(v.x);
            Bs[kk][nq * 4 + 1] = wmma::__float_to_tf32(v.y);
            Bs[kk][nq * 4 + 2] = wmma::__float_to_tf32(v.z);
            Bs[kk][nq * 4 + 3] = wmma::__float_to_tf32(v.w);
        }
        __syncthreads();
        #pragma unroll
        for (int kf = 0; kf < 4; kf++) {
            wmma::fragment<wmma::matrix_a, 16, 16, 8, wmma::precision::tf32, wmma::row_major> af[4];
            wmma::fragment<wmma::matrix_b, 16, 16, 8, wmma::precision::tf32, wmma::row_major> bf[2];
            #pragma unroll
            for (int mi = 0; mi < 4; mi++)
                wmma::load_matrix_sync(af[mi], &As[wm * 64 + mi * 16][kf * 8], 36);
            #pragma unroll
            for (int ni = 0; ni < 2; ni++)
                wmma::load_matrix_sync(bf[ni], &Bs[kf * 8][wn * 32 + ni * 16], 132);
            #pragma unroll
            for (int mi = 0; mi < 4; mi++)
                #pragma unroll
                for (int ni = 0; ni < 2; ni++)
                    wmma::mma_sync(c[mi][ni], af[mi], bf[ni], c[mi][ni]);
        }
        __syncthreads();
    }
    #pragma unroll
    for (int mi = 0; mi < 4; mi++)
        #pragma unroll
        for (int ni = 0; ni < 2; ni++)
            wmma::store_matrix_sync(&g_PE[(size_t)(m0 + wm * 64 + mi * 16) * 512 + j0 + wn * 32 + ni * 16],
                                    c[mi][ni], 512, wmma::mem_row_major);
}

// ---------------- K2: patch rmsnorm rsqrt factor ---------------------------------
__global__ void k_rinv(const float* __restrict__ X) {
    int t = blockIdx.x * blockDim.x + threadIdx.x;
    int b = t >> 12, n = t & (NN - 1);
    const float* p = X + (size_t)b * CC * NN + n;
    float s = 0.0f;
    #pragma unroll 8
    for (int c = 0; c < CC; c++) { float v = p[(size_t)c * NN]; s += v * v; }
    g_RINV[t] = rsqrtf(s * (1.0f / 256.0f) + EPSV);
}

// ---------------- K3: mol rmsnorm + Q projection (+bq) -----------------------------
__global__ void __launch_bounds__(256) k_molq(const float* __restrict__ mol,
                                              const float* __restrict__ wmol,
                                              const float* __restrict__ wq,
                                              const float* __restrict__ bq) {
    __shared__ float x_s[8][512];
    __shared__ float part[8][8][128];
    int row0 = blockIdx.x * 8, jb = blockIdx.y * 128;
    int t = threadIdx.x;
    int w = t >> 5, lane = t & 31;
    float vals[16]; float ss = 0.0f;
    #pragma unroll
    for (int i = 0; i < 16; i++) {
        float v = mol[(row0 + w) * 512 + lane + i * 32];
        vals[i] = v; ss += v * v;
    }
    #pragma unroll
    for (int o = 16; o; o >>= 1) ss += __shfl_xor_sync(0xffffffffu, ss, o);
    float rv = rsqrtf(ss * (1.0f / 512.0f) + EPSV);
    #pragma unroll
    for (int i = 0; i < 16; i++) {
        int m = lane + i * 32;
        float xn = vals[i] * rv * wmol[m];
        x_s[w][m] = xn;
        if (blockIdx.y == 0) g_MOLN[(row0 + w) * 512 + m] = xn;
    }
    __syncthreads();
    int tk = w, tj = lane, j = jb + tj * 4;
    float4 acc[8];
    #pragma unroll
    for (int r = 0; r < 8; r++) acc[r] = make_float4(0.f, 0.f, 0.f, 0.f);
    #pragma unroll 8
    for (int c = tk * 64; c < tk * 64 + 64; c++) {
        float4 w4 = *(const float4*)&wq[(size_t)c * 512 + j];
        #pragma unroll
        for (int r = 0; r < 8; r++) {
            float x = x_s[r][c];
            acc[r].x += x * w4.x; acc[r].y += x * w4.y;
            acc[r].z += x * w4.z; acc[r].w += x * w4.w;
        }
    }
    #pragma unroll
    for (int r = 0; r < 8; r++) *(float4*)&part[tk][r][tj * 4] = acc[r];
    __syncthreads();
    {
        int r = t >> 5, cq = t & 31, j2 = jb + cq * 4;
        float4 s = make_float4(0.f, 0.f, 0.f, 0.f);
        #pragma unroll
        for (int k2 = 0; k2 < 8; k2++) {
            float4 p = *(const float4*)&part[k2][r][cq * 4];
            s.x += p.x; s.y += p.y; s.z += p.z; s.w += p.w;
        }
        float4 bv = *(const float4*)&bq[j2];
        s.x += bv.x; s.y += bv.y; s.z += bv.z; s.w += bv.w;
        *(float4*)&g_Q[(row0 + r) * 512 + j2] = s;
    }
}

// ---------------- K5: tq' = 0.125*wp[c]*(q_h . Wk_h[c,:]); also qbk (cb==0) --------
__global__ void __launch_bounds__(256) k_tq2(const float* __restrict__ wkv,
                                             const float* __restrict__ wp,
                                             const float* __restrict__ bkv,
                                             const float* __restrict__ peb2) {
    __shared__ float As[16][128];
    __shared__ float Bs[16][128];
    __shared__ float cb_s[64];
    int h = blockIdx.x, c0b = blockIdx.y * 128, t = threadIdx.x;
    int tr = t >> 4, tc = t & 15;
    if (t < 16) {
        float4 a = *(const float4*)&bkv[h * 64 + t * 4];
        float4 b = *(const float4*)&peb2[h * 64 + t * 4];
        cb_s[t * 4 + 0] = a.x + b.x;
        cb_s[t * 4 + 1] = a.y + b.y;
        cb_s[t * 4 + 2] = a.z + b.z;
        cb_s[t * 4 + 3] = a.w + b.w;
    }
    __syncthreads();
    // qbk[b,h,e] = q(row t) . (bk+b2) — merged from old k_qbk
    if (blockIdx.y == 0 && t < 128) {
        float s = 0.f;
        #pragma unroll
        for (int d = 0; d < 64; d++) s += g_Q[t * 512 + h * 64 + d] * cb_s[d];
        g_QBK[((t >> 4) * 8 + h) * 16 + (t & 15)] = s;
    }
    float acc[8][8];
    #pragma unroll
    for (int i = 0; i < 8; i++)
        #pragma unroll
        for (int j = 0; j < 8; j++) acc[i][j] = 0.f;
    for (int k0 = 0; k0 < 64; k0 += 16) {
        {
            int r = t >> 1, k8 = (t & 1) * 8;
            const float* src = &g_Q[r * 512 + h * 64 + k0 + k8];
            float4 a0 = *(const float4*)&src[0];
            float4 a1 = *(const float4*)&src[4];
            As[k8 + 0][r] = a0.x; As[k8 + 1][r] = a0.y; As[k8 + 2][r] = a0.z; As[k8 + 3][r] = a0.w;
            As[k8 + 4][r] = a1.x; As[k8 + 5][r] = a1.y; As[k8 + 6][r] = a1.z; As[k8 + 7][r] = a1.w;
        }
        {
            int c = t >> 1, k8 = (t & 1) * 8;
            const float* src = &wkv[(size_t)(c0b + c) * 1024 + h * 64 + k0 + k8];
            float4 v0 = *(const float4*)&src[0];
            float4 v1 = *(const float4*)&src[4];
            Bs[k8 + 0][c] = v0.x; Bs[k8 + 1][c] = v0.y; Bs[k8 + 2][c] = v0.z; Bs[k8 + 3][c] = v0.w;
            Bs[k8 + 4][c] = v1.x; Bs[k8 + 5][c] = v1.y; Bs[k8 + 6][c] = v1.z; Bs[k8 + 7][c] = v1.w;
        }
        __syncthreads();
        #pragma unroll
        for (int kk = 0; kk < 16; kk++) {
            float4 a0 = *(const float4*)&As[kk][tr * 8];
            float4 a1 = *(const float4*)&As[kk][tr * 8 + 4];
            float4 b0 = *(const float4*)&Bs[kk][tc * 8];
            float4 b1 = *(const float4*)&Bs[kk][tc * 8 + 4];
            float a[8] = {a0.x, a0.y, a0.z, a0.w, a1.x, a1.y, a1.z, a1.w};
            float bb[8] = {b0.x, b0.y, b0.z, b0.w, b1.x, b1.y, b1.z, b1.w};
            #pragma unroll
            for (int i = 0; i < 8; i++)
                #pragma unroll
                for (int j = 0; j < 8; j++) acc[i][j] += a[i] * bb[j];
        }
        __syncthreads();
    }
    float4 wp0 = *(const float4*)&wp[c0b + tc * 8];
    float4 wp1 = *(const float4*)&wp[c0b + tc * 8 + 4];
    float wpv[8] = {wp0.x, wp0.y, wp0.z, wp0.w, wp1.x, wp1.y, wp1.z, wp1.w};
    #pragma unroll
    for (int i = 0; i < 8; i++) {
        int r = tr * 8 + i, b = r >> 4, e = r & 15;
        float* dst = &g_TQ[(size_t)(b * 128 + h * 16 + e) * 256 + c0b + tc * 8];
        #pragma unroll
        for (int j = 0; j < 8; j++) dst[j] = acc[i][j] * wpv[j] * 0.125f;
    }
}

// ---------------- K6: S = 0.125*(q_h @ PE_h^T + qbk)  (per h GEMM) -----------------
__global__ void __launch_bounds__(256) k_qpe2() {
    __shared__ float As[16][128];
    __shared__ float Bs[16][128];
    int n0 = blockIdx.x * 128, h = blockIdx.y, t = threadIdx.x;
    int tr = t >> 4, tc = t & 15;
    float acc[8][8];
    #pragma unroll
    for (int i = 0; i < 8; i++)
        #pragma unroll
        for (int j = 0; j < 8; j++) acc[i][j] = 0.f;
    for (int k0 = 0; k0 < 64; k0 += 16) {
        {
            int r = t >> 1, k8 = (t & 1) * 8;
            const float* src = &g_Q[r * 512 + h * 64 + k0 + k8];
            float4 a0 = *(const float4*)&src[0];
            float4 a1 = *(const float4*)&src[4];
            As[k8 + 0][r] = a0.x; As[k8 + 1][r] = a0.y; As[k8 + 2][r] = a0.z; As[k8 + 3][r] = a0.w;
            As[k8 + 4][r] = a1.x; As[k8 + 5][r] = a1.y; As[k8 + 6][r] = a1.z; As[k8 + 7][r] = a1.w;
        }
        {
            int nl = t >> 1, k8 = (t & 1) * 8;
            const float* src = &g_PE[(size_t)(n0 + nl) * 512 + h * 64 + k0 + k8];
            float4 v0 = *(const float4*)&src[0];
            float4 v1 = *(const float4*)&src[4];
            Bs[k8 + 0][nl] = v0.x; Bs[k8 + 1][nl] = v0.y; Bs[k8 + 2][nl] = v0.z; Bs[k8 + 3][nl] = v0.w;
            Bs[k8 + 4][nl] = v1.x; Bs[k8 + 5][nl] = v1.y; Bs[k8 + 6][nl] = v1.z; Bs[k8 + 7][nl] = v1.w;
        }
        __syncthreads();
        #pragma unroll
        for (int kk = 0; kk < 16; kk++) {
            float4 a0 = *(const float4*)&As[kk][tr * 8];
            float4 a1 = *(const float4*)&As[kk][tr * 8 + 4];
            float4 b0 = *(const float4*)&Bs[kk][tc * 8];
            float4 b1 = *(const float4*)&Bs[kk][tc * 8 + 4];
            float a[8] = {a0.x, a0.y, a0.z, a0.w, a1.x, a1.y, a1.z, a1.w};
            float bb[8] = {b0.x, b0.y, b0.z, b0.w, b1.x, b1.y, b1.z, b1.w};
            #pragma unroll
            for (int i = 0; i < 8; i++)
                #pragma unroll
                for (int j = 0; j < 8; j++) acc[i][j] += a[i] * bb[j];
        }
        __syncthreads();
    }
    #pragma unroll
    for (int i = 0; i < 8; i++) {
        int r = tr * 8 + i, b = r >> 4, e = r & 15;
        float qb = g_QBK[(b * 8 + h) * 16 + e];
        float* dst = &g_S[(size_t)((b * 8 + h) * 16 + e) * 4096 + n0 + tc * 8];
        *(float4*)&dst[0] = make_float4((acc[i][0] + qb) * 0.125f, (acc[i][1] + qb) * 0.125f,
                                        (acc[i][2] + qb) * 0.125f, (acc[i][3] + qb) * 0.125f);
        *(float4*)&dst[4] = make_float4((acc[i][4] + qb) * 0.125f, (acc[i][5] + qb) * 0.125f,
                                        (acc[i][6] + qb) * 0.125f, (acc[i][7] + qb) * 0.125f);
    }
}

// ---------------- K7: scores (tf32 TC): S += tq'(0.125 folded) @ (X*rinv) ----------
__global__ void __launch_bounds__(256) k_scores_tc(const float* __restrict__ X) {
    __shared__ __align__(16) float As[128][36];
    __shared__ __align__(16) float Bs[32][132];
    __shared__ __align__(16) float rs[128];
    int n0 = blockIdx.x * 128, b = blockIdx.y, t = threadIdx.x;
    int w = t >> 5, wm = w >> 2, wn = w & 3;
    const float* Xb = X + (size_t)b * CC * NN;
    const float* TQ = g_TQ + (size_t)b * 128 * 256;
    float* Sb = g_S + (size_t)b * 128 * 4096;
    if (t < 32) *(float4*)&rs[t * 4] = *(const float4*)&g_RINV[b * 4096 + n0 + t * 4];
    __syncthreads();
    wmma::fragment<wmma::accumulator, 16, 16, 8, float> c[4][2];
    #pragma unroll
    for (int mi = 0; mi < 4; mi++)
        #pragma unroll
        for (int ni = 0; ni < 2; ni++)
            wmma::load_matrix_sync(c[mi][ni],
                &Sb[(size_t)(wm * 64 + mi * 16) * 4096 + n0 + wn * 32 + ni * 16],
                4096, wmma::mem_row_major);
    for (int c0 = 0; c0 < 256; c0 += 32) {
        #pragma unroll
        for (int r = 0; r < 4; r++) {
            int i = t + 256 * r, row = i >> 3, kq = i & 7;
            float4 v = *(const float4*)&TQ[(size_t)row * 256 + c0 + kq * 4];
            As[row][kq * 4 + 0] = wmma::__float_to_tf32(v.x);
            As[row][kq * 4 + 1] = wmma::__float_to_tf32(v.y);
            As[row][kq * 4 + 2] = wmma::__float_to_tf32(v.z);
            As[row][kq * 4 + 3] = wmma::__float_to_tf32(v.w);
        }
        #pragma unroll
        for (int r = 0; r < 4; r++) {
            int i = t + 256 * r, kk = i >> 5, nq = i & 31;
            float4 v = *(const float4*)&Xb[(size_t)(c0 + kk) * 4096 + n0 + nq * 4];
            Bs[kk][nq * 4 + 0] = wmma::__float_to_tf32(v.x * rs[nq * 4 + 0]);
            Bs[kk][nq * 4 + 1] = wmma::__float_to_tf32(v.y * rs[nq * 4 + 1]);
            Bs[kk][nq * 4 + 2] = wmma::__float_to_tf32(v.z * rs[nq * 4 + 2]);
            Bs[kk][nq * 4 + 3] = wmma::__float_to_tf32(v.w * rs[nq * 4 + 3]);
        }
        __syncthreads();
        #pragma unroll
        for (int kf = 0; kf < 4; kf++) {
            wmma::fragment<wmma::matrix_a, 16, 16, 8, wmma::precision::tf32, wmma::row_major> af[4];
            wmma::fragment<wmma::matrix_b, 16, 16, 8, wmma::precision::tf32, wmma::row_major> bf[2];
            #pragma unroll
            for (int mi = 0; mi < 4; mi++)
                wmma::load_matrix_sync(af[mi], &As[wm * 64 + mi * 16][kf * 8], 36);
            #pragma unroll
            for (int ni = 0; ni < 2; ni++)
                wmma::load_matrix_sync(bf[ni], &Bs[kf * 8][wn * 32 + ni * 16], 132);
            #pragma unroll
            for (int mi = 0; mi < 4; mi++)
                #pragma unroll
                for (int ni = 0; ni < 2; ni++)
                    wmma::mma_sync(c[mi][ni], af[mi], bf[ni], c[mi][ni]);
        }
        __syncthreads();
    }
    #pragma unroll
    for (int mi = 0; mi < 4; mi++)
        #pragma unroll
        for (int ni = 0; ni < 2; ni++)
            wmma::store_matrix_sync(&Sb[(size_t)(wm * 64 + mi * 16) * 4096 + n0 + wn * 32 + ni * 16],
                                    c[mi][ni], 4096, wmma::mem_row_major);
}

// ---------------- K8: softmax over n=4096 ------------------------------------------
__global__ void k_softmax() {
    __shared__ float red[32];
    int row = blockIdx.x;
    float* s = g_S + (size_t)row * NN;
    int t = threadIdx.x;  // 256
    float loc[16];
    float m = -1e30f;
    #pragma unroll
    for (int i = 0; i < 16; i++) { loc[i] = s[t + i * 256]; m = fmaxf(m, loc[i]); }
    m = blk_red<8, true>(m, red);
    float sum = 0.0f;
    #pragma unroll
    for (int i = 0; i < 16; i++) { loc[i] = expf(loc[i] - m); sum += loc[i]; }
    sum = blk_red<8, false>(sum, red);
    float inv = 1.0f / sum;
    #pragma unroll
    for (int i = 0; i < 16; i++) s[t + i * 256] = loc[i] * inv;
}

// ---------------- K9: pa partials (tf32 TC): (p*rinv) @ X^T ------------------------
__global__ void __launch_bounds__(512) k_pa_tc(const float* __restrict__ X) {
    __shared__ __align__(16) float As[128][20];
    __shared__ __align__(16) float Bs[256][20];
    int ks = blockIdx.x, b = blockIdx.y, t = threadIdx.x;
    int nbase = ks * 256;
    int w = t >> 5, wm = w >> 3, wn = w & 7;
    const float* Xb = X + (size_t)b * CC * NN;
    wmma::fragment<wmma::accumulator, 16, 16, 8, float> c[4][2];
    #pragma unroll
    for (int mi = 0; mi < 4; mi++)
        #pragma unroll
        for (int ni = 0; ni < 2; ni++) wmma::fill_fragment(c[mi][ni], 0.0f);
    for (int k0 = 0; k0 < 256; k0 += 16) {
        {
            int row = t >> 2, kq = t & 3;
            int n = nbase + k0 + kq * 4;
            float4 p  = *(const float4*)&g_S[(size_t)(b * 128 + row) * 4096 + n];
            float4 rv = *(const float4*)&g_RINV[b * 4096 + n];
            As[row][kq * 4 + 0] = wmma::__float_to_tf32(p.x * rv.x);
            As[row][kq * 4 + 1] = wmma::__float_to_tf32(p.y * rv.y);
            As[row][kq * 4 + 2] = wmma::__float_to_tf32(p.z * rv.z);
            As[row][kq * 4 + 3] = wmma::__float_to_tf32(p.w * rv.w);
        }
        #pragma unroll
        for (int r = 0; r < 2; r++) {
            int i = t + 512 * r, cc = i >> 2, kq = i & 3;
            float4 v = *(const float4*)&Xb[(size_t)cc * 4096 + nbase + k0 + kq * 4];
            Bs[cc][kq * 4 + 0] = wmma::__float_to_tf32(v.x);
            Bs[cc][kq * 4 + 1] = wmma::__float_to_tf32(v.y);
            Bs[cc][kq * 4 + 2] = wmma::__float_to_tf32(v.z);
            Bs[cc][kq * 4 + 3] = wmma::__float_to_tf32(v.w);
        }
        __syncthreads();
        #pragma unroll
        for (int kf = 0; kf < 2; kf++) {
            wmma::fragment<wmma::matrix_a, 16, 16, 8, wmma::precision::tf32, wmma::row_major> af[4];
            wmma::fragment<wmma::matrix_b, 16, 16, 8, wmma::precision::tf32, wmma::col_major> bf[2];
            #pragma unroll
            for (int mi = 0; mi < 4; mi++)
                wmma::load_matrix_sync(af[mi], &As[wm * 64 + mi * 16][kf * 8], 20);
            #pragma unroll
            for (int ni = 0; ni < 2; ni++)
                wmma::load_matrix_sync(bf[ni], &Bs[wn * 32 + ni * 16][kf * 8], 20);
            #pragma unroll
            for (int mi = 0; mi < 4; mi++)
                #pragma unroll
                for (int ni = 0; ni < 2; ni++)
                    wmma::mma_sync(c[mi][ni], af[mi], bf[ni], c[mi][ni]);
        }
        __syncthreads();
    }
    #pragma unroll
    for (int mi = 0; mi < 4; mi++)
        #pragma unroll
        for (int ni = 0; ni < 2; ni++)
            wmma::store_matrix_sync(
                &g_PAP[(size_t)((ks * 8 + b) * 128 + wm * 64 + mi * 16) * 256 + wn * 32 + ni * 16],
                c[mi][ni], 256, wmma::mem_row_major);
}

// ---------------- K10: ope partials (tf32 TC): p @ (PE_h + bv + b2) ----------------
__global__ void __launch_bounds__(256) k_ppe_tc(const float* __restrict__ bkv,
                                                const float* __restrict__ peb2) {
    __shared__ __align__(16) float As[128][36];
    __shared__ __align__(16) float Bs[32][68];
    __shared__ float bias_s[64];
    int h = blockIdx.x, ks = blockIdx.y, t = threadIdx.x;
    int nb = ks * 512;
    int w = t >> 5, wm = w >> 1, wn = w & 1;
    if (t < 16) {
        float4 bv4 = *(const float4*)&bkv[512 + h * 64 + t * 4];
        float4 b24 = *(const float4*)&peb2[h * 64 + t * 4];
        bias_s[t * 4 + 0] = bv4.x + b24.x;
        bias_s[t * 4 + 1] = bv4.y + b24.y;
        bias_s[t * 4 + 2] = bv4.z + b24.z;
        bias_s[t * 4 + 3] = bv4.w + b24.w;
    }
    __syncthreads();
    wmma::fragment<wmma::accumulator, 16, 16, 8, float> c[2][2];
    #pragma unroll
    for (int mi = 0; mi < 2; mi++)
        #pragma unroll
        for (int ni = 0; ni < 2; ni++) wmma::fill_fragment(c[mi][ni], 0.0f);
    for (int k0 = 0; k0 < 512; k0 += 32) {
        #pragma unroll
        for (int r = 0; r < 4; r++) {
            int i = t + 256 * r, row = i >> 3, kq = i & 7;
            int b = row >> 4, e = row & 15;
            float4 v = *(const float4*)&g_S[(size_t)((b * 8 + h) * 16 + e) * 4096 + nb + k0 + kq * 4];
            As[row][kq * 4 + 0] = wmma::__float_to_tf32(v.x);
            As[row][kq * 4 + 1] = wmma::__float_to_tf32(v.y);
            As[row][kq * 4 + 2] = wmma::__float_to_tf32(v.z);
            As[row][kq * 4 + 3] = wmma::__float_to_tf32(v.w);
        }
        #pragma unroll
        for (int r = 0; r < 2; r++) {
            int i = t + 256 * r, kk = i >> 4, dq = i & 15;
            float4 v = *(const float4*)&g_PE[(size_t)(nb + k0 + kk) * 512 + h * 64 + dq * 4];
            Bs[kk][dq * 4 + 0] = wmma::__float_to_tf32(v.x + bias_s[dq * 4 + 0]);
            Bs[kk][dq * 4 + 1] = wmma::__float_to_tf32(v.y + bias_s[dq * 4 + 1]);
            Bs[kk][dq * 4 + 2] = wmma::__float_to_tf32(v.z + bias_s[dq * 4 + 2]);
            Bs[kk][dq * 4 + 3] = wmma::__float_to_tf32(v.w + bias_s[dq * 4 + 3]);
        }
        __syncthreads();
        #pragma unroll
        for (int kf = 0; kf < 4; kf++) {
            wmma::fragment<wmma::matrix_a, 16, 16, 8, wmma::precision::tf32, wmma::row_major> af[2];
            wmma::fragment<wmma::matrix_b, 16, 16, 8, wmma::precision::tf32, wmma::row_major> bf[2];
            #pragma unroll
            for (int mi = 0; mi < 2; mi++)
                wmma::load_matrix_sync(af[mi], &As[wm * 32 + mi * 16][kf * 8], 36);
            #pragma unroll
            for (int ni = 0; ni < 2; ni++)
                wmma::load_matrix_sync(bf[ni], &Bs[kf * 8][wn * 32 + ni * 16], 68);
            #pragma unroll
            for (int mi = 0; mi < 2; mi++)
                #pragma unroll
                for (int ni = 0; ni < 2; ni++)
                    wmma::mma_sync(c[mi][ni], af[mi], bf[ni], c[mi][ni]);
        }
        __syncthreads();
    }
    #pragma unroll
    for (int mi = 0; mi < 2; mi++)
        #pragma unroll
        for (int ni = 0; ni < 2; ni++)
            wmma::store_matrix_sync(
                &g_OPEP[(size_t)((ks * 8 + h) * 128 + wm * 32 + mi * 16) * 64 + wn * 32 + ni * 16],
                c[mi][ni], 64, wmma::mem_row_major);
}

// ---------------- K11: out0 = (pa*wp-reduced) @ Wv + ope (bias already in ope) -----
__global__ void __launch_bounds__(512) k_out(const float* __restrict__ wkv,
                                             const float* __restrict__ wp) {
    __shared__ float pool[8192];
    __shared__ float ope_s[4][512];
    int row0 = blockIdx.x * 4;
    int t = threadIdx.x;
    for (int idx = t; idx < 8192; idx += 512) {
        int r = idx >> 11, rest = idx & 2047, h = rest >> 8, c = rest & 255;
        int row = row0 + r, b = row >> 4, e = row & 15;
        float s = 0.f;
        #pragma unroll
        for (int ks = 0; ks < 16; ks++)
            s += g_PAP[(size_t)((ks * 8 + b) * 128 + h * 16 + e) * 256 + c];
        pool[idx] = s * wp[c];
    }
    for (int idx = t; idx < 2048; idx += 512) {
        int r = idx >> 9, j = idx & 511;
        int row = row0 + r, b = row >> 4, e = row & 15;
        int h = j >> 6, d = j & 63;
        float s = 0.f;
        #pragma unroll
        for (int ks = 0; ks < 8; ks++)
            s += g_OPEP[(size_t)((ks * 8 + h) * 128 + b * 16 + e) * 64 + d];
        ope_s[r][j] = s;
    }
    __syncthreads();
    int tj = t & 127, tk = t >> 7;
    int h = tj >> 4;
    float4 acc[4];
    #pragma unroll
    for (int r = 0; r < 4; r++) acc[r] = make_float4(0.f, 0.f, 0.f, 0.f);
    #pragma unroll 4
    for (int c = tk * 64; c < tk * 64 + 64; c++) {
        float4 w4 = *(const float4*)&wkv[(size_t)c * 1024 + 512 + tj * 4];
        #pragma unroll
        for (int r = 0; r < 4; r++) {
            float p = pool[r * 2048 + h * 256 + c];
            acc[r].x += p * w4.x; acc[r].y += p * w4.y;
            acc[r].z += p * w4.z; acc[r].w += p * w4.w;
        }
    }
    __syncthreads();
    #pragma unroll
    for (int r = 0; r < 4; r++) *(float4*)&pool[(tk * 4 + r) * 512 + tj * 4] = acc[r];
    __syncthreads();
    {
        int r = t >> 7, j0 = (t & 127) * 4;
        float4 s = make_float4(0.f, 0.f, 0.f, 0.f);
        #pragma unroll
        for (int k2 = 0; k2 < 4; k2++) {
            float4 p = *(const float4*)&pool[(k2 * 4 + r) * 512 + j0];
            s.x += p.x; s.y += p.y; s.z += p.z; s.w += p.w;
        }
        float4 op = *(const float4*)&ope_s[r][j0];
        s.x += op.x; s.y += op.y; s.z += op.z; s.w += op.w;
        *(float4*)&g_ATT0[(row0 + r) * 512 + j0] = s;
    }
}

// ---------------- K12: proj + residual ---------------------------------------------
__global__ void __launch_bounds__(256) k_proj(const float* __restrict__ wproj,
                                              const float* __restrict__ bproj) {
    __shared__ float x_s[8][512];
    __shared__ float part[8][8][128];
    int row0 = blockIdx.x * 8, jb = blockIdx.y * 128, t = threadIdx.x;
    for (int idx = t; idx < 4096; idx += 256)
        x_s[idx >> 9][idx & 511] = g_ATT0[(row0 + (idx >> 9)) * 512 + (idx & 511)];
    __syncthreads();
    int tk = t >> 5, tj = t & 31, j = jb + tj * 4;
    float4 acc[8];
    #pragma unroll
    for (int r = 0; r < 8; r++) acc[r] = make_float4(0.f, 0.f, 0.f, 0.f);
    #pragma unroll 8
    for (int c = tk * 64; c < tk * 64 + 64; c++) {
        float4 w4 = *(const float4*)&wproj[(size_t)c * 512 + j];
        #pragma unroll
        for (int r = 0; r < 8; r++) {
            float x = x_s[r][c];
            acc[r].x += x * w4.x; acc[r].y += x * w4.y;
            acc[r].z += x * w4.z; acc[r].w += x * w4.w;
        }
    }
    #pragma unroll
    for (int r = 0; r < 8; r++) *(float4*)&part[tk][r][tj * 4] = acc[r];
    __syncthreads();
    {
        int r = t >> 5, cq = t & 31, j2 = jb + cq * 4;
        float4 s = make_float4(0.f, 0.f, 0.f, 0.f);
        #pragma unroll
        for (int k2 = 0; k2 < 8; k2++) {
            float4 p = *(const float4*)&part[k2][r][cq * 4];
            s.x += p.x; s.y += p.y; s.z += p.z; s.w += p.w;
        }
        float4 bp = *(const float4*)&bproj[j2];
        float4 mn = *(const float4*)&g_MOLN[(row0 + r) * 512 + j2];
        s.x += bp.x + mn.x; s.y += bp.y + mn.y;
        s.z += bp.z + mn.z; s.w += bp.w + mn.w;
        *(float4*)&g_ATT[(row0 + r) * 512 + j2] = s;
    }
}

// ---------------- K13: ffn1 (fused rmsnorm) + gelu ----------------------------------
__global__ void __launch_bounds__(256) k_ffn1(const float* __restrict__ nw,
                                              const float* __restrict__ w1,
                                              const float* __restrict__ b1) {
    __shared__ float x_s[8][512];
    __shared__ float part[8][8][128];
    int row0 = blockIdx.x * 8, jb = blockIdx.y * 128, t = threadIdx.x;
    int w = t >> 5, lane = t & 31;
    {
        float vals[16]; float ss = 0.f;
        #pragma unroll
        for (int i = 0; i < 16; i++) {
            float v = g_ATT[(row0 + w) * 512 + lane + i * 32];
            vals[i] = v; ss += v * v;
        }
        #pragma unroll
        for (int o = 16; o; o >>= 1) ss += __shfl_xor_sync(0xffffffffu, ss, o);
        float rv = rsqrtf(ss * (1.0f / 512.0f) + EPSV);
        #pragma unroll
        for (int i = 0; i < 16; i++) {
            int m = lane + i * 32;
            x_s[w][m] = vals[i] * rv * nw[m];
        }
    }
    __syncthreads();
    int tk = t >> 5, tj = t & 31, j = jb + tj * 4;
    float4 acc[8];
    #pragma unroll
    for (int r = 0; r < 8; r++) acc[r] = make_float4(0.f, 0.f, 0.f, 0.f);
    #pragma unroll 8
    for (int c = tk * 64; c < tk * 64 + 64; c++) {
        float4 w4 = *(const float4*)&w1[(size_t)c * 2048 + j];
        #pragma unroll
        for (int r = 0; r < 8; r++) {
            float x = x_s[r][c];
            acc[r].x += x * w4.x; acc[r].y += x * w4.y;
            acc[r].z += x * w4.z; acc[r].w += x * w4.w;
        }
    }
    #pragma unroll
    for (int r = 0; r < 8; r++) *(float4*)&part[tk][r][tj * 4] = acc[r];
    __syncthreads();
    {
        int r = t >> 5, cq = t & 31, j2 = jb + cq * 4;
        float4 s = make_float4(0.f, 0.f, 0.f, 0.f);
        #pragma unroll
        for (int k2 = 0; k2 < 8; k2++) {
            float4 p = *(const float4*)&part[k2][r][cq * 4];
            s.x += p.x; s.y += p.y; s.z += p.z; s.w += p.w;
        }
        float4 bb = *(const float4*)&b1[j2];
        float4 o;
        o.x = geluf(s.x + bb.x); o.y = geluf(s.y + bb.y);
        o.z = geluf(s.z + bb.z); o.w = geluf(s.w + bb.w);
        *(float4*)&g_H1[(size_t)(row0 + r) * 2048 + j2] = o;
    }
}

// ---------------- K14: ffn2 + residual ----------------------------------------------
__global__ void __launch_bounds__(512) k_ffn2(const float* __restrict__ w2,
                                              const float* __restrict__ b2,
                                              float* __restrict__ out) {
    __shared__ float pool[8192];
    int row0 = blockIdx.x * 4, jb = blockIdx.y * 128, t = threadIdx.x;
    for (int idx = t; idx < 8192; idx += 512)
        pool[idx] = g_H1[(size_t)(row0 + (idx >> 11)) * 2048 + (idx & 2047)];
    __syncthreads();
    int tk = t >> 5, tj = t & 31, j = jb + tj * 4;
    float4 acc[4];
    #pragma unroll
    for (int r = 0; r < 4; r++) acc[r] = make_float4(0.f, 0.f, 0.f, 0.f);
    #pragma unroll 8
    for (int c = tk * 128; c < tk * 128 + 128; c++) {
        float4 w4 = *(const float4*)&w2[(size_t)c * 512 + j];
        #pragma unroll
        for (int r = 0; r < 4; r++) {
            float x = pool[r * 2048 + c];
            acc[r].x += x * w4.x; acc[r].y += x * w4.y;
            acc[r].z += x * w4.z; acc[r].w += x * w4.w;
        }
    }
    __syncthreads();
    #pragma unroll
    for (int r = 0; r < 4; r++) *(float4*)&pool[tk * 512 + r * 128 + tj * 4] = acc[r];
    __syncthreads();
    {
        int r = t >> 7, cq = t & 127;
        float s = 0.f;
        #pragma unroll
        for (int k2 = 0; k2 < 16; k2++) s += pool[k2 * 512 + r * 128 + cq];
        int j2 = jb + cq;
        out[(row0 + r) * 512 + j2] = s + b2[j2] + g_ATT[(row0 + r) * 512 + j2];
    }
}

// ---------------- launch -------------------------------------------------------------
extern "C" void kernel_launch(void* const* d_in, const int* in_sizes, int n_in,
                              void* d_out, int out_size) {
    const float* patch   = (const float*)d_in[0];
    const float* mol     = (const float*)d_in[1];
    const float* pe_w1   = (const float*)d_in[2];
    const float* pe_b1   = (const float*)d_in[3];
    const float* pe_w2   = (const float*)d_in[4];
    const float* pe_b2   = (const float*)d_in[5];
    const float* wq      = (const float*)d_in[6];
    const float* bq      = (const float*)d_in[7];
    const float* wkv     = (const float*)d_in[8];
    const float* bkv     = (const float*)d_in[9];
    const float* wproj   = (const float*)d_in[10];
    const float* bproj   = (const float*)d_in[11];
    const float* nmolw   = (const float*)d_in[12];
    const float* npatchw = (const float*)d_in[13];
    const float* ffn_w1  = (const float*)d_in[14];
    const float* ffn_b1  = (const float*)d_in[15];
    const float* ffn_w2  = (const float*)d_in[16];
    const float* ffn_b2  = (const float*)d_in[17];
    const float* ffn_nw  = (const float*)d_in[18];
    float* out = (float*)d_out;
    (void)in_sizes; (void)n_in; (void)out_size;

    k_gel      <<<NN, 256>>>(pe_w1, pe_b1);
    k_peg_tc   <<<dim3(32, 4), 256>>>(pe_w2);
    k_rinv     <<<(BB * NN) / 256, 256>>>(patch);
    k_molq     <<<dim3(16, 4), 256>>>(mol, nmolw, wq, bq);
    k_tq2      <<<dim3(8, 2), 256>>>(wkv, npatchw, bkv, pe_b2);
    k_qpe2     <<<dim3(32, 8), 256>>>();
    k_scores_tc<<<dim3(32, 8), 256>>>(patch);
    k_softmax  <<<BB * 128, 256>>>();
    k_pa_tc    <<<dim3(16, 8), 512>>>(patch);
    k_ppe_tc   <<<dim3(8, 8), 256>>>(bkv, pe_b2);
    k_out      <<<32, 512>>>(wkv, npatchw);
    k_proj     <<<dim3(16, 4), 256>>>(wproj, bproj);
    k_ffn1     <<<dim3(16, 16), 256>>>(ffn_nw, ffn_w1, ffn_b1);
    k_ffn2     <<<dim3(32, 4), 512>>>(ffn_w2, ffn_b2, out);
}

// round 11
// speedup vs baseline: 1.3761x; 1.0051x over previous
#include <cuda_runtime.h>
#include <mma.h>
#include <math.h>

using namespace nvcuda;

#define BB 8
#define CC 256
#define NN 4096
#define MM 512
#define EE 16
#define NH 8
#define FFNH 2048
#define EPSV 1.1920929e-07f

// ------------- scratch (__device__ globals; no allocation allowed) ---------------
__device__ float g_PE  [NN * MM];             // pos_enc G@W2 (NO bias)
__device__ float g_RINV[BB * NN];             // patch rmsnorm rsqrt (written by k_scores_tc)
__device__ float g_Q   [128 * 512];           // q rows=(b,e) (includes bq)
__device__ float g_MOLN[128 * 512];           // normalized mol (residual)
__device__ float g_TQ  [BB * 128 * 256];      // tq' rows=(b, h*16+e), wp & 0.125 folded
__device__ float g_QBK [BB * NH * EE];        // q . (bk + b2)  (per b,h,e)
__device__ float g_S   [(size_t)BB * 128 * NN];       // scores/probs  16.8 MB
__device__ float g_PAP [(size_t)16 * BB * 128 * 256]; // pa partials   16.8 MB
__device__ float g_OPEP[8 * 8 * 128 * 64];    // p@(pe+bv+b2) partials
__device__ float g_ATT0[128 * 512];           // attention out (pre-proj)
__device__ float g_ATT [128 * 512];           // attended (post residual)
__device__ float g_H1  [128 * 2048];          // ffn hidden

__device__ __forceinline__ float geluf(float x) {
    return 0.5f * x * (1.0f + erff(x * 0.70710678118654752440f));
}

template <int NWARPS, bool DOMAX>
__device__ __forceinline__ float blk_red(float v, float* red) {
    #pragma unroll
    for (int o = 16; o; o >>= 1) {
        float t = __shfl_xor_sync(0xffffffffu, v, o);
        v = DOMAX ? fmaxf(v, t) : v + t;
    }
    if ((threadIdx.x & 31) == 0) red[threadIdx.x >> 5] = v;
    __syncthreads();
    if (threadIdx.x < 32) {
        float r = (threadIdx.x < NWARPS) ? red[threadIdx.x] : (DOMAX ? -1e30f : 0.0f);
        #pragma unroll
        for (int o = NWARPS >> 1; o; o >>= 1) {
            float t = __shfl_xor_sync(0xffffffffu, r, o);
            r = DOMAX ? fmaxf(r, t) : r + t;
        }
        if (threadIdx.x == 0) red[0] = r;
    }
    __syncthreads();
    float s = red[0];
    __syncthreads();
    return s;
}

// ---------------- K1: PE = gelu(coords@W1+b1) @ W2 (tf32 TC, gelu fused) -----------
__global__ void __launch_bounds__(256) k_peg_tc(const float* __restrict__ w1,
                                                const float* __restrict__ b1,
                                                const float* __restrict__ w2) {
    __shared__ __align__(16) float As[128][36];
    __shared__ __align__(16) float Bs[32][132];
    int m0 = blockIdx.x * 128, j0 = blockIdx.y * 128, t = threadIdx.x;
    int w = t >> 5, wm = w >> 2, wn = w & 3;
    wmma::fragment<wmma::accumulator, 16, 16, 8, float> c[4][2];
    #pragma unroll
    for (int mi = 0; mi < 4; mi++)
        #pragma unroll
        for (int ni = 0; ni < 2; ni++) wmma::fill_fragment(c[mi][ni], 0.0f);
    for (int c0 = 0; c0 < 256; c0 += 32) {
        #pragma unroll
        for (int r = 0; r < 4; r++) {
            int i = t + 256 * r, row = i >> 3, kq = i & 7;
            int n = m0 + row;
            float cd = (float)(n >> 8)        * 0.0625f;
            float chc = (float)((n >> 4) & 15) * 0.0625f;
            float cw = (float)(n & 15)        * 0.0625f;
            int k = c0 + kq * 4;
            float4 wd = *(const float4*)&w1[k];
            float4 wh = *(const float4*)&w1[256 + k];
            float4 ww = *(const float4*)&w1[512 + k];
            float4 bb = *(const float4*)&b1[k];
            As[row][kq * 4 + 0] = wmma::__float_to_tf32(geluf(cd * wd.x + chc * wh.x + cw * ww.x + bb.x));
            As[row][kq * 4 + 1] = wmma::__float_to_tf32(geluf(cd * wd.y + chc * wh.y + cw * ww.y + bb.y));
            As[row][kq * 4 + 2] = wmma::__float_to_tf32(geluf(cd * wd.z + chc * wh.z + cw * ww.z + bb.z));
            As[row][kq * 4 + 3] = wmma::__float_to_tf32(geluf(cd * wd.w + chc * wh.w + cw * ww.w + bb.w));
        }
        #pragma unroll
        for (int r = 0; r < 4; r++) {
            int i = t + 256 * r, kk = i >> 5, nq = i & 31;
            float4 v = *(const float4*)&w2[(size_t)(c0 + kk) * 512 + j0 + nq * 4];
            Bs[kk][nq * 4 + 0] = wmma::__float_to_tf32(v.x);
            Bs[kk][nq * 4 + 1] = wmma::__float_to_tf32(v.y);
            Bs[kk][nq * 4 + 2] = wmma::__float_to_tf32(v.z);
            Bs[kk][nq * 4 + 3] = wmma::__float_to_tf32(v.w);
        }
        __syncthreads();
        #pragma unroll
        for (int kf = 0; kf < 4; kf++) {
            wmma::fragment<wmma::matrix_a, 16, 16, 8, wmma::precision::tf32, wmma::row_major> af[4];
            wmma::fragment<wmma::matrix_b, 16, 16, 8, wmma::precision::tf32, wmma::row_major> bf[2];
            #pragma unroll
            for (int mi = 0; mi < 4; mi++)
                wmma::load_matrix_sync(af[mi], &As[wm * 64 + mi * 16][kf * 8], 36);
            #pragma unroll
            for (int ni = 0; ni < 2; ni++)
                wmma::load_matrix_sync(bf[ni], &Bs[kf * 8][wn * 32 + ni * 16], 132);
            #pragma unroll
            for (int mi = 0; mi < 4; mi++)
                #pragma unroll
                for (int ni = 0; ni < 2; ni++)
                    wmma::mma_sync(c[mi][ni], af[mi], bf[ni], c[mi][ni]);
        }
        __syncthreads();
    }
    #pragma unroll
    for (int mi = 0; mi < 4; mi++)
        #pragma unroll
        for (int ni = 0; ni < 2; ni++)
            wmma::store_matrix_sync(&g_PE[(size_t)(m0 + wm * 64 + mi * 16) * 512 + j0 + wn * 32 + ni * 16],
                                    c[mi][ni], 512, wmma::mem_row_major);
}

// ---------------- K3: mol rmsnorm + Q projection (+bq) -----------------------------
__global__ void __launch_bounds__(256) k_molq(const float* __restrict__ mol,
                                              const float* __restrict__ wmol,
                                              const float* __restrict__ wq,
                                              const float* __restrict__ bq) {
    __shared__ float x_s[8][512];
    __shared__ float part[8][8][128];
    int row0 = blockIdx.x * 8, jb = blockIdx.y * 128;
    int t = threadIdx.x;
    int w = t >> 5, lane = t & 31;
    float vals[16]; float ss = 0.0f;
    #pragma unroll
    for (int i = 0; i < 16; i++) {
        float v = mol[(row0 + w) * 512 + lane + i * 32];
        vals[i] = v; ss += v * v;
    }
    #pragma unroll
    for (int o = 16; o; o >>= 1) ss += __shfl_xor_sync(0xffffffffu, ss, o);
    float rv = rsqrtf(ss * (1.0f / 512.0f) + EPSV);
    #pragma unroll
    for (int i = 0; i < 16; i++) {
        int m = lane + i * 32;
        float xn = vals[i] * rv * wmol[m];
        x_s[w][m] = xn;
        if (blockIdx.y == 0) g_MOLN[(row0 + w) * 512 + m] = xn;
    }
    __syncthreads();
    int tk = w, tj = lane, j = jb + tj * 4;
    float4 acc[8];
    #pragma unroll
    for (int r = 0; r < 8; r++) acc[r] = make_float4(0.f, 0.f, 0.f, 0.f);
    #pragma unroll 8
    for (int c = tk * 64; c < tk * 64 + 64; c++) {
        float4 w4 = *(const float4*)&wq[(size_t)c * 512 + j];
        #pragma unroll
        for (int r = 0; r < 8; r++) {
            float x = x_s[r][c];
            acc[r].x += x * w4.x; acc[r].y += x * w4.y;
            acc[r].z += x * w4.z; acc[r].w += x * w4.w;
        }
    }
    #pragma unroll
    for (int r = 0; r < 8; r++) *(float4*)&part[tk][r][tj * 4] = acc[r];
    __syncthreads();
    {
        int r = t >> 5, cq = t & 31, j2 = jb + cq * 4;
        float4 s = make_float4(0.f, 0.f, 0.f, 0.f);
        #pragma unroll
        for (int k2 = 0; k2 < 8; k2++) {
            float4 p = *(const float4*)&part[k2][r][cq * 4];
            s.x += p.x; s.y += p.y; s.z += p.z; s.w += p.w;
        }
        float4 bv = *(const float4*)&bq[j2];
        s.x += bv.x; s.y += bv.y; s.z += bv.z; s.w += bv.w;
        *(float4*)&g_Q[(row0 + r) * 512 + j2] = s;
    }
}

// ---------------- K5: tq' = 0.125*wp[c]*(q_h . Wk_h[c,:]); also qbk (cb==0) --------
__global__ void __launch_bounds__(256) k_tq2(const float* __restrict__ wkv,
                                             const float* __restrict__ wp,
                                             const float* __restrict__ bkv,
                                             const float* __restrict__ peb2) {
    __shared__ float As[16][128];
    __shared__ float Bs[16][128];
    __shared__ float cb_s[64];
    int h = blockIdx.x, c0b = blockIdx.y * 128, t = threadIdx.x;
    int tr = t >> 4, tc = t & 15;
    if (t < 16) {
        float4 a = *(const float4*)&bkv[h * 64 + t * 4];
        float4 b = *(const float4*)&peb2[h * 64 + t * 4];
        cb_s[t * 4 + 0] = a.x + b.x;
        cb_s[t * 4 + 1] = a.y + b.y;
        cb_s[t * 4 + 2] = a.z + b.z;
        cb_s[t * 4 + 3] = a.w + b.w;
    }
    __syncthreads();
    if (blockIdx.y == 0 && t < 128) {
        float s = 0.f;
        #pragma unroll
        for (int d = 0; d < 64; d++) s += g_Q[t * 512 + h * 64 + d] * cb_s[d];
        g_QBK[((t >> 4) * 8 + h) * 16 + (t & 15)] = s;
    }
    float acc[8][8];
    #pragma unroll
    for (int i = 0; i < 8; i++)
        #pragma unroll
        for (int j = 0; j < 8; j++) acc[i][j] = 0.f;
    for (int k0 = 0; k0 < 64; k0 += 16) {
        {
            int r = t >> 1, k8 = (t & 1) * 8;
            const float* src = &g_Q[r * 512 + h * 64 + k0 + k8];
            float4 a0 = *(const float4*)&src[0];
            float4 a1 = *(const float4*)&src[4];
            As[k8 + 0][r] = a0.x; As[k8 + 1][r] = a0.y; As[k8 + 2][r] = a0.z; As[k8 + 3][r] = a0.w;
            As[k8 + 4][r] = a1.x; As[k8 + 5][r] = a1.y; As[k8 + 6][r] = a1.z; As[k8 + 7][r] = a1.w;
        }
        {
            int c = t >> 1, k8 = (t & 1) * 8;
            const float* src = &wkv[(size_t)(c0b + c) * 1024 + h * 64 + k0 + k8];
            float4 v0 = *(const float4*)&src[0];
            float4 v1 = *(const float4*)&src[4];
            Bs[k8 + 0][c] = v0.x; Bs[k8 + 1][c] = v0.y; Bs[k8 + 2][c] = v0.z; Bs[k8 + 3][c] = v0.w;
            Bs[k8 + 4][c] = v1.x; Bs[k8 + 5][c] = v1.y; Bs[k8 + 6][c] = v1.z; Bs[k8 + 7][c] = v1.w;
        }
        __syncthreads();
        #pragma unroll
        for (int kk = 0; kk < 16; kk++) {
            float4 a0 = *(const float4*)&As[kk][tr * 8];
            float4 a1 = *(const float4*)&As[kk][tr * 8 + 4];
            float4 b0 = *(const float4*)&Bs[kk][tc * 8];
            float4 b1 = *(const float4*)&Bs[kk][tc * 8 + 4];
            float a[8] = {a0.x, a0.y, a0.z, a0.w, a1.x, a1.y, a1.z, a1.w};
            float bb[8] = {b0.x, b0.y, b0.z, b0.w, b1.x, b1.y, b1.z, b1.w};
            #pragma unroll
            for (int i = 0; i < 8; i++)
                #pragma unroll
                for (int j = 0; j < 8; j++) acc[i][j] += a[i] * bb[j];
        }
        __syncthreads();
    }
    float4 wp0 = *(const float4*)&wp[c0b + tc * 8];
    float4 wp1 = *(const float4*)&wp[c0b + tc * 8 + 4];
    float wpv[8] = {wp0.x, wp0.y, wp0.z, wp0.w, wp1.x, wp1.y, wp1.z, wp1.w};
    #pragma unroll
    for (int i = 0; i < 8; i++) {
        int r = tr * 8 + i, b = r >> 4, e = r & 15;
        float* dst = &g_TQ[(size_t)(b * 128 + h * 16 + e) * 256 + c0b + tc * 8];
        #pragma unroll
        for (int j = 0; j < 8; j++) dst[j] = acc[i][j] * wpv[j] * 0.125f;
    }
}

// ---------------- K6: S = 0.125*(q_h @ PE_h^T + qbk)  (tf32 TC) --------------------
// grid(32 nt, 8 h), 256 thr (2m x 4n warps). K chunks: 0..31, 32..63 = q@PE^T;
// chunk 64..95 carries the qbk bias (A col0 = 0.125*qbk, B row0 = ones).
__global__ void __launch_bounds__(256) k_qpe_tc() {
    __shared__ __align__(16) float As[128][36];
    __shared__ __align__(16) float Bs[32][132];
    int n0 = blockIdx.x * 128, h = blockIdx.y, t = threadIdx.x;
    int w = t >> 5, wm = w >> 2, wn = w & 3;
    wmma::fragment<wmma::accumulator, 16, 16, 8, float> c[4][2];
    #pragma unroll
    for (int mi = 0; mi < 4; mi++)
        #pragma unroll
        for (int ni = 0; ni < 2; ni++) wmma::fill_fragment(c[mi][ni], 0.0f);
    for (int c0 = 0; c0 < 96; c0 += 32) {
        #pragma unroll
        for (int r = 0; r < 4; r++) {
            int i = t + 256 * r, row = i >> 3, kq = i & 7;
            if (c0 < 64) {
                float4 v = *(const float4*)&g_Q[row * 512 + h * 64 + c0 + kq * 4];
                As[row][kq * 4 + 0] = wmma::__float_to_tf32(0.125f * v.x);
                As[row][kq * 4 + 1] = wmma::__float_to_tf32(0.125f * v.y);
                As[row][kq * 4 + 2] = wmma::__float_to_tf32(0.125f * v.z);
                As[row][kq * 4 + 3] = wmma::__float_to_tf32(0.125f * v.w);
            } else {
                float qb = 0.f;
                if (kq == 0) {
                    int b = row >> 4, e = row & 15;
                    qb = 0.125f * g_QBK[(b * 8 + h) * 16 + e];
                }
                As[row][kq * 4 + 0] = wmma::__float_to_tf32(qb);
                As[row][kq * 4 + 1] = 0.f;
                As[row][kq * 4 + 2] = 0.f;
                As[row][kq * 4 + 3] = 0.f;
            }
        }
        #pragma unroll
        for (int r = 0; r < 4; r++) {
            int i = t + 256 * r, n = i >> 3, kq = i & 7;
            if (c0 < 64) {
                float4 v = *(const float4*)&g_PE[(size_t)(n0 + n) * 512 + h * 64 + c0 + kq * 4];
                Bs[kq * 4 + 0][n] = wmma::__float_to_tf32(v.x);
                Bs[kq * 4 + 1][n] = wmma::__float_to_tf32(v.y);
                Bs[kq * 4 + 2][n] = wmma::__float_to_tf32(v.z);
                Bs[kq * 4 + 3][n] = wmma::__float_to_tf32(v.w);
            } else {
                Bs[kq * 4 + 0][n] = (kq == 0) ? 1.0f : 0.0f;
                Bs[kq * 4 + 1][n] = 0.0f;
                Bs[kq * 4 + 2][n] = 0.0f;
                Bs[kq * 4 + 3][n] = 0.0f;
            }
        }
        __syncthreads();
        #pragma unroll
        for (int kf = 0; kf < 4; kf++) {
            wmma::fragment<wmma::matrix_a, 16, 16, 8, wmma::precision::tf32, wmma::row_major> af[4];
            wmma::fragment<wmma::matrix_b, 16, 16, 8, wmma::precision::tf32, wmma::row_major> bf[2];
            #pragma unroll
            for (int mi = 0; mi < 4; mi++)
                wmma::load_matrix_sync(af[mi], &As[wm * 64 + mi * 16][kf * 8], 36);
            #pragma unroll
            for (int ni = 0; ni < 2; ni++)
                wmma::load_matrix_sync(bf[ni], &Bs[kf * 8][wn * 32 + ni * 16], 132);
            #pragma unroll
            for (int mi = 0; mi < 4; mi++)
                #pragma unroll
                for (int ni = 0; ni < 2; ni++)
                    wmma::mma_sync(c[mi][ni], af[mi], bf[ni], c[mi][ni]);
        }
        __syncthreads();
    }
    #pragma unroll
    for (int mi = 0; mi < 4; mi++) {
        int r0 = wm * 64 + mi * 16;       // consecutive 16 rows, same b
        int b = r0 >> 4;
        float* dst = &g_S[(size_t)((b * 8 + h) * 16) * 4096 + n0 + wn * 32];
        #pragma unroll
        for (int ni = 0; ni < 2; ni++)
            wmma::store_matrix_sync(dst + ni * 16, c[mi][ni], 4096, wmma::mem_row_major);
    }
}

// ---------------- K7: scores (tf32 TC, rinv fused): S += tq' @ (X*rinv) ------------
__global__ void __launch_bounds__(256) k_scores_tc(const float* __restrict__ X) {
    __shared__ __align__(16) float As[128][36];
    __shared__ __align__(16) float Bs[32][132];
    __shared__ __align__(16) float rs[128];
    __shared__ float ss2[256];
    int n0 = blockIdx.x * 128, b = blockIdx.y, t = threadIdx.x;
    int w = t >> 5, wm = w >> 2, wn = w & 3;
    const float* Xb = X + (size_t)b * CC * NN;
    const float* TQ = g_TQ + (size_t)b * 128 * 256;
    float* Sb = g_S + (size_t)b * 128 * 4096;
    // phase 1: rmsnorm rsqrt for this n-tile (warms L2 with the X we reuse below)
    {
        int tn = t & 127, chh = t >> 7;
        const float* xp = Xb + (size_t)(chh * 128) * 4096 + n0 + tn;
        float s0 = 0.f, s1 = 0.f, s2 = 0.f, s3 = 0.f;
        #pragma unroll 4
        for (int c = 0; c < 128; c += 4) {
            float v0 = xp[(size_t)(c + 0) * 4096];
            float v1 = xp[(size_t)(c + 1) * 4096];
            float v2 = xp[(size_t)(c + 2) * 4096];
            float v3 = xp[(size_t)(c + 3) * 4096];
            s0 += v0 * v0; s1 += v1 * v1; s2 += v2 * v2; s3 += v3 * v3;
        }
        ss2[t] = (s0 + s1) + (s2 + s3);
    }
    __syncthreads();
    if (t < 128) {
        float rv = rsqrtf((ss2[t] + ss2[t + 128]) * (1.0f / 256.0f) + EPSV);
        rs[t] = rv;
        g_RINV[b * 4096 + n0 + t] = rv;   // byproduct for k_pa_tc
    }
    __syncthreads();
    wmma::fragment<wmma::accumulator, 16, 16, 8, float> c[4][2];
    #pragma unroll
    for (int mi = 0; mi < 4; mi++)
        #pragma unroll
        for (int ni = 0; ni < 2; ni++)
            wmma::load_matrix_sync(c[mi][ni],
                &Sb[(size_t)(wm * 64 + mi * 16) * 4096 + n0 + wn * 32 + ni * 16],
                4096, wmma::mem_row_major);
    for (int c0 = 0; c0 < 256; c0 += 32) {
        #pragma unroll
        for (int r = 0; r < 4; r++) {
            int i = t + 256 * r, row = i >> 3, kq = i & 7;
            float4 v = *(const float4*)&TQ[(size_t)row * 256 + c0 + kq * 4];
            As[row][kq * 4 + 0] = wmma::__float_to_tf32(v.x);
            As[row][kq * 4 + 1] = wmma::__float_to_tf32(v.y);
            As[row][kq * 4 + 2] = wmma::__float_to_tf32(v.z);
            As[row][kq * 4 + 3] = wmma::__float_to_tf32(v.w);
        }
        #pragma unroll
        for (int r = 0; r < 4; r++) {
            int i = t + 256 * r, kk = i >> 5, nq = i & 31;
            float4 v = *(const float4*)&Xb[(size_t)(c0 + kk) * 4096 + n0 + nq * 4];
            Bs[kk][nq * 4 + 0] = wmma::__float_to_tf32(v.x * rs[nq * 4 + 0]);
            Bs[kk][nq * 4 + 1] = wmma::__float_to_tf32(v.y * rs[nq * 4 + 1]);
            Bs[kk][nq * 4 + 2] = wmma::__float_to_tf32(v.z * rs[nq * 4 + 2]);
            Bs[kk][nq * 4 + 3] = wmma::__float_to_tf32(v.w * rs[nq * 4 + 3]);
        }
        __syncthreads();
        #pragma unroll
        for (int kf = 0; kf < 4; kf++) {
            wmma::fragment<wmma::matrix_a, 16, 16, 8, wmma::precision::tf32, wmma::row_major> af[4];
            wmma::fragment<wmma::matrix_b, 16, 16, 8, wmma::precision::tf32, wmma::row_major> bf[2];
            #pragma unroll
            for (int mi = 0; mi < 4; mi++)
                wmma::load_matrix_sync(af[mi], &As[wm * 64 + mi * 16][kf * 8], 36);
            #pragma unroll
            for (int ni = 0; ni < 2; ni++)
                wmma::load_matrix_sync(bf[ni], &Bs[kf * 8][wn * 32 + ni * 16], 132);
            #pragma unroll
            for (int mi = 0; mi < 4; mi++)
                #pragma unroll
                for (int ni = 0; ni < 2; ni++)
                    wmma::mma_sync(c[mi][ni], af[mi], bf[ni], c[mi][ni]);
        }
        __syncthreads();
    }
    #pragma unroll
    for (int mi = 0; mi < 4; mi++)
        #pragma unroll
        for (int ni = 0; ni < 2; ni++)
            wmma::store_matrix_sync(&Sb[(size_t)(wm * 64 + mi * 16) * 4096 + n0 + wn * 32 + ni * 16],
                                    c[mi][ni], 4096, wmma::mem_row_major);
}

// ---------------- K8: softmax over n=4096 ------------------------------------------
__global__ void k_softmax() {
    __shared__ float red[32];
    int row = blockIdx.x;
    float* s = g_S + (size_t)row * NN;
    int t = threadIdx.x;  // 256
    float loc[16];
    float m = -1e30f;
    #pragma unroll
    for (int i = 0; i < 16; i++) { loc[i] = s[t + i * 256]; m = fmaxf(m, loc[i]); }
    m = blk_red<8, true>(m, red);
    float sum = 0.0f;
    #pragma unroll
    for (int i = 0; i < 16; i++) { loc[i] = __expf(loc[i] - m); sum += loc[i]; }
    sum = blk_red<8, false>(sum, red);
    float inv = 1.0f / sum;
    #pragma unroll
    for (int i = 0; i < 16; i++) s[t + i * 256] = loc[i] * inv;
}

// ---------------- K9: pa partials (tf32 TC): (p*rinv) @ X^T ------------------------
__global__ void __launch_bounds__(512) k_pa_tc(const float* __restrict__ X) {
    __shared__ __align__(16) float As[128][20];
    __shared__ __align__(16) float Bs[256][20];
    int ks = blockIdx.x, b = blockIdx.y, t = threadIdx.x;
    int nbase = ks * 256;
    int w = t >> 5, wm = w >> 3, wn = w & 7;
    const float* Xb = X + (size_t)b * CC * NN;
    wmma::fragment<wmma::accumulator, 16, 16, 8, float> c[4][2];
    #pragma unroll
    for (int mi = 0; mi < 4; mi++)
        #pragma unroll
        for (int ni = 0; ni < 2; ni++) wmma::fill_fragment(c[mi][ni], 0.0f);
    for (int k0 = 0; k0 < 256; k0 += 16) {
        {
            int row = t >> 2, kq = t & 3;
            int n = nbase + k0 + kq * 4;
            float4 p  = *(const float4*)&g_S[(size_t)(b * 128 + row) * 4096 + n];
            float4 rv = *(const float4*)&g_RINV[b * 4096 + n];
            As[row][kq * 4 + 0] = wmma::__float_to_tf32(p.x * rv.x);
            As[row][kq * 4 + 1] = wmma::__float_to_tf32(p.y * rv.y);
            As[row][kq * 4 + 2] = wmma::__float_to_tf32(p.z * rv.z);
            As[row][kq * 4 + 3] = wmma::__float_to_tf32(p.w * rv.w);
        }
        #pragma unroll
        for (int r = 0; r < 2; r++) {
            int i = t + 512 * r, cc = i >> 2, kq = i & 3;
            float4 v = *(const float4*)&Xb[(size_t)cc * 4096 + nbase + k0 + kq * 4];
            Bs[cc][kq * 4 + 0] = wmma::__float_to_tf32(v.x);
            Bs[cc][kq * 4 + 1] = wmma::__float_to_tf32(v.y);
            Bs[cc][kq * 4 + 2] = wmma::__float_to_tf32(v.z);
            Bs[cc][kq * 4 + 3] = wmma::__float_to_tf32(v.w);
        }
        __syncthreads();
        #pragma unroll
        for (int kf = 0; kf < 2; kf++) {
            wmma::fragment<wmma::matrix_a, 16, 16, 8, wmma::precision::tf32, wmma::row_major> af[4];
            wmma::fragment<wmma::matrix_b, 16, 16, 8, wmma::precision::tf32, wmma::col_major> bf[2];
            #pragma unroll
            for (int mi = 0; mi < 4; mi++)
                wmma::load_matrix_sync(af[mi], &As[wm * 64 + mi * 16][kf * 8], 20);
            #pragma unroll
            for (int ni = 0; ni < 2; ni++)
                wmma::load_matrix_sync(bf[ni], &Bs[wn * 32 + ni * 16][kf * 8], 20);
            #pragma unroll
            for (int mi = 0; mi < 4; mi++)
                #pragma unroll
                for (int ni = 0; ni < 2; ni++)
                    wmma::mma_sync(c[mi][ni], af[mi], bf[ni], c[mi][ni]);
        }
        __syncthreads();
    }
    #pragma unroll
    for (int mi = 0; mi < 4; mi++)
        #pragma unroll
        for (int ni = 0; ni < 2; ni++)
            wmma::store_matrix_sync(
                &g_PAP[(size_t)((ks * 8 + b) * 128 + wm * 64 + mi * 16) * 256 + wn * 32 + ni * 16],
                c[mi][ni], 256, wmma::mem_row_major);
}

// ---------------- K10: ope partials (tf32 TC): p @ (PE_h + bv + b2) ----------------
__global__ void __launch_bounds__(256) k_ppe_tc(const float* __restrict__ bkv,
                                                const float* __restrict__ peb2) {
    __shared__ __align__(16) float As[128][36];
    __shared__ __align__(16) float Bs[32][68];
    __shared__ float bias_s[64];
    int h = blockIdx.x, ks = blockIdx.y, t = threadIdx.x;
    int nb = ks * 512;
    int w = t >> 5, wm = w >> 1, wn = w & 1;
    if (t < 16) {
        float4 bv4 = *(const float4*)&bkv[512 + h * 64 + t * 4];
        float4 b24 = *(const float4*)&peb2[h * 64 + t * 4];
        bias_s[t * 4 + 0] = bv4.x + b24.x;
        bias_s[t * 4 + 1] = bv4.y + b24.y;
        bias_s[t * 4 + 2] = bv4.z + b24.z;
        bias_s[t * 4 + 3] = bv4.w + b24.w;
    }
    __syncthreads();
    wmma::fragment<wmma::accumulator, 16, 16, 8, float> c[2][2];
    #pragma unroll
    for (int mi = 0; mi < 2; mi++)
        #pragma unroll
        for (int ni = 0; ni < 2; ni++) wmma::fill_fragment(c[mi][ni], 0.0f);
    for (int k0 = 0; k0 < 512; k0 += 32) {
        #pragma unroll
        for (int r = 0; r < 4; r++) {
            int i = t + 256 * r, row = i >> 3, kq = i & 7;
            int b = row >> 4, e = row & 15;
            float4 v = *(const float4*)&g_S[(size_t)((b * 8 + h) * 16 + e) * 4096 + nb + k0 + kq * 4];
            As[row][kq * 4 + 0] = wmma::__float_to_tf32(v.x);
            As[row][kq * 4 + 1] = wmma::__float_to_tf32(v.y);
            As[row][kq * 4 + 2] = wmma::__float_to_tf32(v.z);
            As[row][kq * 4 + 3] = wmma::__float_to_tf32(v.w);
        }
        #pragma unroll
        for (int r = 0; r < 2; r++) {
            int i = t + 256 * r, kk = i >> 4, dq = i & 15;
            float4 v = *(const float4*)&g_PE[(size_t)(nb + k0 + kk) * 512 + h * 64 + dq * 4];
            Bs[kk][dq * 4 + 0] = wmma::__float_to_tf32(v.x + bias_s[dq * 4 + 0]);
            Bs[kk][dq * 4 + 1] = wmma::__float_to_tf32(v.y + bias_s[dq * 4 + 1]);
            Bs[kk][dq * 4 + 2] = wmma::__float_to_tf32(v.z + bias_s[dq * 4 + 2]);
            Bs[kk][dq * 4 + 3] = wmma::__float_to_tf32(v.w + bias_s[dq * 4 + 3]);
        }
        __syncthreads();
        #pragma unroll
        for (int kf = 0; kf < 4; kf++) {
            wmma::fragment<wmma::matrix_a, 16, 16, 8, wmma::precision::tf32, wmma::row_major> af[2];
            wmma::fragment<wmma::matrix_b, 16, 16, 8, wmma::precision::tf32, wmma::row_major> bf[2];
            #pragma unroll
            for (int mi = 0; mi < 2; mi++)
                wmma::load_matrix_sync(af[mi], &As[wm * 32 + mi * 16][kf * 8], 36);
            #pragma unroll
            for (int ni = 0; ni < 2; ni++)
                wmma::load_matrix_sync(bf[ni], &Bs[kf * 8][wn * 32 + ni * 16], 68);
            #pragma unroll
            for (int mi = 0; mi < 2; mi++)
                #pragma unroll
                for (int ni = 0; ni < 2; ni++)
                    wmma::mma_sync(c[mi][ni], af[mi], bf[ni], c[mi][ni]);
        }
        __syncthreads();
    }
    #pragma unroll
    for (int mi = 0; mi < 2; mi++)
        #pragma unroll
        for (int ni = 0; ni < 2; ni++)
            wmma::store_matrix_sync(
                &g_OPEP[(size_t)((ks * 8 + h) * 128 + wm * 32 + mi * 16) * 64 + wn * 32 + ni * 16],
                c[mi][ni], 64, wmma::mem_row_major);
}

// ---------------- K11: out0 = (pa*wp-reduced) @ Wv + ope ---------------------------
__global__ void __launch_bounds__(512) k_out(const float* __restrict__ wkv,
                                             const float* __restrict__ wp) {
    __shared__ float pool[8192];
    __shared__ float ope_s[4][512];
    int row0 = blockIdx.x * 4;
    int t = threadIdx.x;
    for (int idx = t; idx < 8192; idx += 512) {
        int r = idx >> 11, rest = idx & 2047, h = rest >> 8, c = rest & 255;
        int row = row0 + r, b = row >> 4, e = row & 15;
        float s = 0.f;
        #pragma unroll
        for (int ks = 0; ks < 16; ks++)
            s += g_PAP[(size_t)((ks * 8 + b) * 128 + h * 16 + e) * 256 + c];
        pool[idx] = s * wp[c];
    }
    for (int idx = t; idx < 2048; idx += 512) {
        int r = idx >> 9, j = idx & 511;
        int row = row0 + r, b = row >> 4, e = row & 15;
        int h = j >> 6, d = j & 63;
        float s = 0.f;
        #pragma unroll
        for (int ks = 0; ks < 8; ks++)
            s += g_OPEP[(size_t)((ks * 8 + h) * 128 + b * 16 + e) * 64 + d];
        ope_s[r][j] = s;
    }
    __syncthreads();
    int tj = t & 127, tk = t >> 7;
    int h = tj >> 4;
    float4 acc[4];
    #pragma unroll
    for (int r = 0; r < 4; r++) acc[r] = make_float4(0.f, 0.f, 0.f, 0.f);
    #pragma unroll 4
    for (int c = tk * 64; c < tk * 64 + 64; c++) {
        float4 w4 = *(const float4*)&wkv[(size_t)c * 1024 + 512 + tj * 4];
        #pragma unroll
        for (int r = 0; r < 4; r++) {
            float p = pool[r * 2048 + h * 256 + c];
            acc[r].x += p * w4.x; acc[r].y += p * w4.y;
            acc[r].z += p * w4.z; acc[r].w += p * w4.w;
        }
    }
    __syncthreads();
    #pragma unroll
    for (int r = 0; r < 4; r++) *(float4*)&pool[(tk * 4 + r) * 512 + tj * 4] = acc[r];
    __syncthreads();
    {
        int r = t >> 7, j0 = (t & 127) * 4;
        float4 s = make_float4(0.f, 0.f, 0.f, 0.f);
        #pragma unroll
        for (int k2 = 0; k2 < 4; k2++) {
            float4 p = *(const float4*)&pool[(k2 * 4 + r) * 512 + j0];
            s.x += p.x; s.y += p.y; s.z += p.z; s.w += p.w;
        }
        float4 op = *(const float4*)&ope_s[r][j0];
        s.x += op.x; s.y += op.y; s.z += op.z; s.w += op.w;
        *(float4*)&g_ATT0[(row0 + r) * 512 + j0] = s;
    }
}

// ---------------- K12: proj + residual ---------------------------------------------
__global__ void __launch_bounds__(256) k_proj(const float* __restrict__ wproj,
                                              const float* __restrict__ bproj) {
    __shared__ float x_s[8][512];
    __shared__ float part[8][8][128];
    int row0 = blockIdx.x * 8, jb = blockIdx.y * 128, t = threadIdx.x;
    for (int idx = t; idx < 4096; idx += 256)
        x_s[idx >> 9][idx & 511] = g_ATT0[(row0 + (idx >> 9)) * 512 + (idx & 511)];
    __syncthreads();
    int tk = t >> 5, tj = t & 31, j = jb + tj * 4;
    float4 acc[8];
    #pragma unroll
    for (int r = 0; r < 8; r++) acc[r] = make_float4(0.f, 0.f, 0.f, 0.f);
    #pragma unroll 8
    for (int c = tk * 64; c < tk * 64 + 64; c++) {
        float4 w4 = *(const float4*)&wproj[(size_t)c * 512 + j];
        #pragma unroll
        for (int r = 0; r < 8; r++) {
            float x = x_s[r][c];
            acc[r].x += x * w4.x; acc[r].y += x * w4.y;
            acc[r].z += x * w4.z; acc[r].w += x * w4.w;
        }
    }
    #pragma unroll
    for (int r = 0; r < 8; r++) *(float4*)&part[tk][r][tj * 4] = acc[r];
    __syncthreads();
    {
        int r = t >> 5, cq = t & 31, j2 = jb + cq * 4;
        float4 s = make_float4(0.f, 0.f, 0.f, 0.f);
        #pragma unroll
        for (int k2 = 0; k2 < 8; k2++) {
            float4 p = *(const float4*)&part[k2][r][cq * 4];
            s.x += p.x; s.y += p.y; s.z += p.z; s.w += p.w;
        }
        float4 bp = *(const float4*)&bproj[j2];
        float4 mn = *(const float4*)&g_MOLN[(row0 + r) * 512 + j2];
        s.x += bp.x + mn.x; s.y += bp.y + mn.y;
        s.z += bp.z + mn.z; s.w += bp.w + mn.w;
        *(float4*)&g_ATT[(row0 + r) * 512 + j2] = s;
    }
}

// ---------------- K13: ffn1 (fused rmsnorm) + gelu ----------------------------------
__global__ void __launch_bounds__(256) k_ffn1(const float* __restrict__ nw,
                                              const float* __restrict__ w1,
                                              const float* __restrict__ b1) {
    __shared__ float x_s[8][512];
    __shared__ float part[8][8][128];
    int row0 = blockIdx.x * 8, jb = blockIdx.y * 128, t = threadIdx.x;
    int w = t >> 5, lane = t & 31;
    {
        float vals[16]; float ss = 0.f;
        #pragma unroll
        for (int i = 0; i < 16; i++) {
            float v = g_ATT[(row0 + w) * 512 + lane + i * 32];
            vals[i] = v; ss += v * v;
        }
        #pragma unroll
        for (int o = 16; o; o >>= 1) ss += __shfl_xor_sync(0xffffffffu, ss, o);
        float rv = rsqrtf(ss * (1.0f / 512.0f) + EPSV);
        #pragma unroll
        for (int i = 0; i < 16; i++) {
            int m = lane + i * 32;
            x_s[w][m] = vals[i] * rv * nw[m];
        }
    }
    __syncthreads();
    int tk = t >> 5, tj = t & 31, j = jb + tj * 4;
    float4 acc[8];
    #pragma unroll
    for (int r = 0; r < 8; r++) acc[r] = make_float4(0.f, 0.f, 0.f, 0.f);
    #pragma unroll 8
    for (int c = tk * 64; c < tk * 64 + 64; c++) {
        float4 w4 = *(const float4*)&w1[(size_t)c * 2048 + j];
        #pragma unroll
        for (int r = 0; r < 8; r++) {
            float x = x_s[r][c];
            acc[r].x += x * w4.x; acc[r].y += x * w4.y;
            acc[r].z += x * w4.z; acc[r].w += x * w4.w;
        }
    }
    #pragma unroll
    for (int r = 0; r < 8; r++) *(float4*)&part[tk][r][tj * 4] = acc[r];
    __syncthreads();
    {
        int r = t >> 5, cq = t & 31, j2 = jb + cq * 4;
        float4 s = make_float4(0.f, 0.f, 0.f, 0.f);
        #pragma unroll
        for (int k2 = 0; k2 < 8; k2++) {
            float4 p = *(const float4*)&part[k2][r][cq * 4];
            s.x += p.x; s.y += p.y; s.z += p.z; s.w += p.w;
        }
        float4 bb = *(const float4*)&b1[j2];
        float4 o;
        o.x = geluf(s.x + bb.x); o.y = geluf(s.y + bb.y);
        o.z = geluf(s.z + bb.z); o.w = geluf(s.w + bb.w);
        *(float4*)&g_H1[(size_t)(row0 + r) * 2048 + j2] = o;
    }
}

// ---------------- K14: ffn2 + residual ----------------------------------------------
__global__ void __launch_bounds__(512) k_ffn2(const float* __restrict__ w2,
                                              const float* __restrict__ b2,
                                              float* __restrict__ out) {
    __shared__ float pool[8192];
    int row0 = blockIdx.x * 4, jb = blockIdx.y * 128, t = threadIdx.x;
    for (int idx = t; idx < 8192; idx += 512)
        pool[idx] = g_H1[(size_t)(row0 + (idx >> 11)) * 2048 + (idx & 2047)];
    __syncthreads();
    int tk = t >> 5, tj = t & 31, j = jb + tj * 4;
    float4 acc[4];
    #pragma unroll
    for (int r = 0; r < 4; r++) acc[r] = make_float4(0.f, 0.f, 0.f, 0.f);
    #pragma unroll 8
    for (int c = tk * 128; c < tk * 128 + 128; c++) {
        float4 w4 = *(const float4*)&w2[(size_t)c * 512 + j];
        #pragma unroll
        for (int r = 0; r < 4; r++) {
            float x = pool[r * 2048 + c];
            acc[r].x += x * w4.x; acc[r].y += x * w4.y;
            acc[r].z += x * w4.z; acc[r].w += x * w4.w;
        }
    }
    __syncthreads();
    #pragma unroll
    for (int r = 0; r < 4; r++) *(float4*)&pool[tk * 512 + r * 128 + tj * 4] = acc[r];
    __syncthreads();
    {
        int r = t >> 7, cq = t & 127;
        float s = 0.f;
        #pragma unroll
        for (int k2 = 0; k2 < 16; k2++) s += pool[k2 * 512 + r * 128 + cq];
        int j2 = jb + cq;
        out[(row0 + r) * 512 + j2] = s + b2[j2] + g_ATT[(row0 + r) * 512 + j2];
    }
}

// ---------------- launch -------------------------------------------------------------
extern "C" void kernel_launch(void* const* d_in, const int* in_sizes, int n_in,
                              void* d_out, int out_size) {
    const float* patch   = (const float*)d_in[0];
    const float* mol     = (const float*)d_in[1];
    const float* pe_w1   = (const float*)d_in[2];
    const float* pe_b1   = (const float*)d_in[3];
    const float* pe_w2   = (const float*)d_in[4];
    const float* pe_b2   = (const float*)d_in[5];
    const float* wq      = (const float*)d_in[6];
    const float* bq      = (const float*)d_in[7];
    const float* wkv     = (const float*)d_in[8];
    const float* bkv     = (const float*)d_in[9];
    const float* wproj   = (const float*)d_in[10];
    const float* bproj   = (const float*)d_in[11];
    const float* nmolw   = (const float*)d_in[12];
    const float* npatchw = (const float*)d_in[13];
    const float* ffn_w1  = (const float*)d_in[14];
    const float* ffn_b1  = (const float*)d_in[15];
    const float* ffn_w2  = (const float*)d_in[16];
    const float* ffn_b2  = (const float*)d_in[17];
    const float* ffn_nw  = (const float*)d_in[18];
    float* out = (float*)d_out;
    (void)in_sizes; (void)n_in; (void)out_size;

    k_peg_tc   <<<dim3(32, 4), 256>>>(pe_w1, pe_b1, pe_w2);
    k_molq     <<<dim3(16, 4), 256>>>(mol, nmolw, wq, bq);
    k_tq2      <<<dim3(8, 2), 256>>>(wkv, npatchw, bkv, pe_b2);
    k_qpe_tc   <<<dim3(32, 8), 256>>>();
    k_scores_tc<<<dim3(32, 8), 256>>>(patch);
    k_softmax  <<<BB * 128, 256>>>();
    k_pa_tc    <<<dim3(16, 8), 512>>>(patch);
    k_ppe_tc   <<<dim3(8, 8), 256>>>(bkv, pe_b2);
    k_out      <<<32, 512>>>(wkv, npatchw);
    k_proj     <<<dim3(16, 4), 256>>>(wproj, bproj);
    k_ffn1     <<<dim3(16, 16), 256>>>(ffn_nw, ffn_w1, ffn_b1);
    k_ffn2     <<<dim3(32, 4), 512>>>(ffn_w2, ffn_b2, out);
}

// round 12
// speedup vs baseline: 1.4113x; 1.0256x over previous
#include <cuda_runtime.h>
#include <mma.h>
#include <math.h>

using namespace nvcuda;

#define BB 8
#define CC 256
#define NN 4096
#define MM 512
#define EE 16
#define NH 8
#define FFNH 2048
#define EPSV 1.1920929e-07f

// ------------- scratch (__device__ globals; no allocation allowed) ---------------
__device__ float g_PE  [NN * MM];             // pos_enc G@W2 (NO bias)
__device__ float g_RINV[BB * NN];             // patch rmsnorm rsqrt (written by k_scores_tc)
__device__ float g_Q   [128 * 512];           // q rows=(b,e) (includes bq)
__device__ float g_MOLN[128 * 512];           // normalized mol (residual)
__device__ float g_TQ  [BB * 128 * 256];      // tq' rows=(b, h*16+e), wp & 0.125 folded
__device__ float g_S   [(size_t)BB * 128 * NN];       // scores/probs  16.8 MB
__device__ float g_PAP [(size_t)16 * BB * 128 * 256]; // pa partials   16.8 MB
__device__ float g_OPEP[8 * 8 * 128 * 64];    // p@(pe+bv+b2) partials
__device__ float g_ATT0[128 * 512];           // attention out (pre-proj)
__device__ float g_ATT [128 * 512];           // attended (post residual)
__device__ float g_H1  [128 * 2048];          // ffn hidden

__device__ __forceinline__ float geluf(float x) {
    return 0.5f * x * (1.0f + erff(x * 0.70710678118654752440f));
}

template <int NWARPS, bool DOMAX>
__device__ __forceinline__ float blk_red(float v, float* red) {
    #pragma unroll
    for (int o = 16; o; o >>= 1) {
        float t = __shfl_xor_sync(0xffffffffu, v, o);
        v = DOMAX ? fmaxf(v, t) : v + t;
    }
    if ((threadIdx.x & 31) == 0) red[threadIdx.x >> 5] = v;
    __syncthreads();
    if (threadIdx.x < 32) {
        float r = (threadIdx.x < NWARPS) ? red[threadIdx.x] : (DOMAX ? -1e30f : 0.0f);
        #pragma unroll
        for (int o = NWARPS >> 1; o; o >>= 1) {
            float t = __shfl_xor_sync(0xffffffffu, r, o);
            r = DOMAX ? fmaxf(r, t) : r + t;
        }
        if (threadIdx.x == 0) red[0] = r;
    }
    __syncthreads();
    float s = red[0];
    __syncthreads();
    return s;
}

// ---------------- K1: PE = gelu(coords@W1+b1) @ W2 (tf32 TC, gelu fused) -----------
__global__ void __launch_bounds__(256) k_peg_tc(const float* __restrict__ w1,
                                                const float* __restrict__ b1,
                                                const float* __restrict__ w2) {
    __shared__ __align__(16) float As[128][36];
    __shared__ __align__(16) float Bs[32][132];
    int m0 = blockIdx.x * 128, j0 = blockIdx.y * 128, t = threadIdx.x;
    int w = t >> 5, wm = w >> 2, wn = w & 3;
    wmma::fragment<wmma::accumulator, 16, 16, 8, float> c[4][2];
    #pragma unroll
    for (int mi = 0; mi < 4; mi++)
        #pragma unroll
        for (int ni = 0; ni < 2; ni++) wmma::fill_fragment(c[mi][ni], 0.0f);
    for (int c0 = 0; c0 < 256; c0 += 32) {
        #pragma unroll
        for (int r = 0; r < 4; r++) {
            int i = t + 256 * r, row = i >> 3, kq = i & 7;
            int n = m0 + row;
            float cd = (float)(n >> 8)        * 0.0625f;
            float chc = (float)((n >> 4) & 15) * 0.0625f;
            float cw = (float)(n & 15)        * 0.0625f;
            int k = c0 + kq * 4;
            float4 wd = *(const float4*)&w1[k];
            float4 wh = *(const float4*)&w1[256 + k];
            float4 ww = *(const float4*)&w1[512 + k];
            float4 bb = *(const float4*)&b1[k];
            As[row][kq * 4 + 0] = wmma::__float_to_tf32(geluf(cd * wd.x + chc * wh.x + cw * ww.x + bb.x));
            As[row][kq * 4 + 1] = wmma::__float_to_tf32(geluf(cd * wd.y + chc * wh.y + cw * ww.y + bb.y));
            As[row][kq * 4 + 2] = wmma::__float_to_tf32(geluf(cd * wd.z + chc * wh.z + cw * ww.z + bb.z));
            As[row][kq * 4 + 3] = wmma::__float_to_tf32(geluf(cd * wd.w + chc * wh.w + cw * ww.w + bb.w));
        }
        #pragma unroll
        for (int r = 0; r < 4; r++) {
            int i = t + 256 * r, kk = i >> 5, nq = i & 31;
            float4 v = *(const float4*)&w2[(size_t)(c0 + kk) * 512 + j0 + nq * 4];
            Bs[kk][nq * 4 + 0] = wmma::__float_to_tf32(v.x);
            Bs[kk][nq * 4 + 1] = wmma::__float_to_tf32(v.y);
            Bs[kk][nq * 4 + 2] = wmma::__float_to_tf32(v.z);
            Bs[kk][nq * 4 + 3] = wmma::__float_to_tf32(v.w);
        }
        __syncthreads();
        #pragma unroll
        for (int kf = 0; kf < 4; kf++) {
            wmma::fragment<wmma::matrix_a, 16, 16, 8, wmma::precision::tf32, wmma::row_major> af[4];
            wmma::fragment<wmma::matrix_b, 16, 16, 8, wmma::precision::tf32, wmma::row_major> bf[2];
            #pragma unroll
            for (int mi = 0; mi < 4; mi++)
                wmma::load_matrix_sync(af[mi], &As[wm * 64 + mi * 16][kf * 8], 36);
            #pragma unroll
            for (int ni = 0; ni < 2; ni++)
                wmma::load_matrix_sync(bf[ni], &Bs[kf * 8][wn * 32 + ni * 16], 132);
            #pragma unroll
            for (int mi = 0; mi < 4; mi++)
                #pragma unroll
                for (int ni = 0; ni < 2; ni++)
                    wmma::mma_sync(c[mi][ni], af[mi], bf[ni], c[mi][ni]);
        }
        __syncthreads();
    }
    #pragma unroll
    for (int mi = 0; mi < 4; mi++)
        #pragma unroll
        for (int ni = 0; ni < 2; ni++)
            wmma::store_matrix_sync(&g_PE[(size_t)(m0 + wm * 64 + mi * 16) * 512 + j0 + wn * 32 + ni * 16],
                                    c[mi][ni], 512, wmma::mem_row_major);
}

// ---------------- K2: mol rmsnorm + Q projection (+bq) -----------------------------
__global__ void __launch_bounds__(256) k_molq(const float* __restrict__ mol,
                                              const float* __restrict__ wmol,
                                              const float* __restrict__ wq,
                                              const float* __restrict__ bq) {
    __shared__ float x_s[8][512];
    __shared__ float part[8][8][128];
    int row0 = blockIdx.x * 8, jb = blockIdx.y * 128;
    int t = threadIdx.x;
    int w = t >> 5, lane = t & 31;
    float vals[16]; float ss = 0.0f;
    #pragma unroll
    for (int i = 0; i < 16; i++) {
        float v = mol[(row0 + w) * 512 + lane + i * 32];
        vals[i] = v; ss += v * v;
    }
    #pragma unroll
    for (int o = 16; o; o >>= 1) ss += __shfl_xor_sync(0xffffffffu, ss, o);
    float rv = rsqrtf(ss * (1.0f / 512.0f) + EPSV);
    #pragma unroll
    for (int i = 0; i < 16; i++) {
        int m = lane + i * 32;
        float xn = vals[i] * rv * wmol[m];
        x_s[w][m] = xn;
        if (blockIdx.y == 0) g_MOLN[(row0 + w) * 512 + m] = xn;
    }
    __syncthreads();
    int tk = w, tj = lane, j = jb + tj * 4;
    float4 acc[8];
    #pragma unroll
    for (int r = 0; r < 8; r++) acc[r] = make_float4(0.f, 0.f, 0.f, 0.f);
    #pragma unroll 8
    for (int c = tk * 64; c < tk * 64 + 64; c++) {
        float4 w4 = *(const float4*)&wq[(size_t)c * 512 + j];
        #pragma unroll
        for (int r = 0; r < 8; r++) {
            float x = x_s[r][c];
            acc[r].x += x * w4.x; acc[r].y += x * w4.y;
            acc[r].z += x * w4.z; acc[r].w += x * w4.w;
        }
    }
    #pragma unroll
    for (int r = 0; r < 8; r++) *(float4*)&part[tk][r][tj * 4] = acc[r];
    __syncthreads();
    {
        int r = t >> 5, cq = t & 31, j2 = jb + cq * 4;
        float4 s = make_float4(0.f, 0.f, 0.f, 0.f);
        #pragma unroll
        for (int k2 = 0; k2 < 8; k2++) {
            float4 p = *(const float4*)&part[k2][r][cq * 4];
            s.x += p.x; s.y += p.y; s.z += p.z; s.w += p.w;
        }
        float4 bv = *(const float4*)&bq[j2];
        s.x += bv.x; s.y += bv.y; s.z += bv.z; s.w += bv.w;
        *(float4*)&g_Q[(row0 + r) * 512 + j2] = s;
    }
}

// ---------------- K3: tq' = 0.125*wp[c]*(q_h . Wk_h[c,:]) --------------------------
// (qbk term deleted: it is constant per softmax row, hence softmax-invariant)
__global__ void __launch_bounds__(256) k_tq2(const float* __restrict__ wkv,
                                             const float* __restrict__ wp) {
    __shared__ float As[16][128];
    __shared__ float Bs[16][128];
    int h = blockIdx.x, c0b = blockIdx.y * 128, t = threadIdx.x;
    int tr = t >> 4, tc = t & 15;
    float acc[8][8];
    #pragma unroll
    for (int i = 0; i < 8; i++)
        #pragma unroll
        for (int j = 0; j < 8; j++) acc[i][j] = 0.f;
    for (int k0 = 0; k0 < 64; k0 += 16) {
        {
            int r = t >> 1, k8 = (t & 1) * 8;
            const float* src = &g_Q[r * 512 + h * 64 + k0 + k8];
            float4 a0 = *(const float4*)&src[0];
            float4 a1 = *(const float4*)&src[4];
            As[k8 + 0][r] = a0.x; As[k8 + 1][r] = a0.y; As[k8 + 2][r] = a0.z; As[k8 + 3][r] = a0.w;
            As[k8 + 4][r] = a1.x; As[k8 + 5][r] = a1.y; As[k8 + 6][r] = a1.z; As[k8 + 7][r] = a1.w;
        }
        {
            int c = t >> 1, k8 = (t & 1) * 8;
            const float* src = &wkv[(size_t)(c0b + c) * 1024 + h * 64 + k0 + k8];
            float4 v0 = *(const float4*)&src[0];
            float4 v1 = *(const float4*)&src[4];
            Bs[k8 + 0][c] = v0.x; Bs[k8 + 1][c] = v0.y; Bs[k8 + 2][c] = v0.z; Bs[k8 + 3][c] = v0.w;
            Bs[k8 + 4][c] = v1.x; Bs[k8 + 5][c] = v1.y; Bs[k8 + 6][c] = v1.z; Bs[k8 + 7][c] = v1.w;
        }
        __syncthreads();
        #pragma unroll
        for (int kk = 0; kk < 16; kk++) {
            float4 a0 = *(const float4*)&As[kk][tr * 8];
            float4 a1 = *(const float4*)&As[kk][tr * 8 + 4];
            float4 b0 = *(const float4*)&Bs[kk][tc * 8];
            float4 b1 = *(const float4*)&Bs[kk][tc * 8 + 4];
            float a[8] = {a0.x, a0.y, a0.z, a0.w, a1.x, a1.y, a1.z, a1.w};
            float bb[8] = {b0.x, b0.y, b0.z, b0.w, b1.x, b1.y, b1.z, b1.w};
            #pragma unroll
            for (int i = 0; i < 8; i++)
                #pragma unroll
                for (int j = 0; j < 8; j++) acc[i][j] += a[i] * bb[j];
        }
        __syncthreads();
    }
    float4 wp0 = *(const float4*)&wp[c0b + tc * 8];
    float4 wp1 = *(const float4*)&wp[c0b + tc * 8 + 4];
    float wpv[8] = {wp0.x, wp0.y, wp0.z, wp0.w, wp1.x, wp1.y, wp1.z, wp1.w};
    #pragma unroll
    for (int i = 0; i < 8; i++) {
        int r = tr * 8 + i, b = r >> 4, e = r & 15;
        float* dst = &g_TQ[(size_t)(b * 128 + h * 16 + e) * 256 + c0b + tc * 8];
        #pragma unroll
        for (int j = 0; j < 8; j++) dst[j] = acc[i][j] * wpv[j] * 0.125f;
    }
}

// ---------------- K4: S = (0.125*q_h) @ PE_h^T  (tf32 TC, K=64, col-major B) -------
// PE is [n][k] row-major in gmem == col-major B with no transpose staging needed.
__global__ void __launch_bounds__(256) k_qpe_tc() {
    __shared__ __align__(16) float As[128][36];
    __shared__ __align__(16) float Bs[128][36];   // PE rows (n), 32 k-cols per chunk
    int n0 = blockIdx.x * 128, h = blockIdx.y, t = threadIdx.x;
    int w = t >> 5, wm = w >> 2, wn = w & 3;
    wmma::fragment<wmma::accumulator, 16, 16, 8, float> c[4][2];
    #pragma unroll
    for (int mi = 0; mi < 4; mi++)
        #pragma unroll
        for (int ni = 0; ni < 2; ni++) wmma::fill_fragment(c[mi][ni], 0.0f);
    for (int c0 = 0; c0 < 64; c0 += 32) {
        #pragma unroll
        for (int r = 0; r < 4; r++) {
            int i = t + 256 * r, row = i >> 3, kq = i & 7;
            float4 v = *(const float4*)&g_Q[row * 512 + h * 64 + c0 + kq * 4];
            As[row][kq * 4 + 0] = wmma::__float_to_tf32(0.125f * v.x);
            As[row][kq * 4 + 1] = wmma::__float_to_tf32(0.125f * v.y);
            As[row][kq * 4 + 2] = wmma::__float_to_tf32(0.125f * v.z);
            As[row][kq * 4 + 3] = wmma::__float_to_tf32(0.125f * v.w);
        }
        #pragma unroll
        for (int r = 0; r < 4; r++) {
            int i = t + 256 * r, row = i >> 3, kq = i & 7;
            float4 v = *(const float4*)&g_PE[(size_t)(n0 + row) * 512 + h * 64 + c0 + kq * 4];
            Bs[row][kq * 4 + 0] = wmma::__float_to_tf32(v.x);
            Bs[row][kq * 4 + 1] = wmma::__float_to_tf32(v.y);
            Bs[row][kq * 4 + 2] = wmma::__float_to_tf32(v.z);
            Bs[row][kq * 4 + 3] = wmma::__float_to_tf32(v.w);
        }
        __syncthreads();
        #pragma unroll
        for (int kf = 0; kf < 4; kf++) {
            wmma::fragment<wmma::matrix_a, 16, 16, 8, wmma::precision::tf32, wmma::row_major> af[4];
            wmma::fragment<wmma::matrix_b, 16, 16, 8, wmma::precision::tf32, wmma::col_major> bf[2];
            #pragma unroll
            for (int mi = 0; mi < 4; mi++)
                wmma::load_matrix_sync(af[mi], &As[wm * 64 + mi * 16][kf * 8], 36);
            #pragma unroll
            for (int ni = 0; ni < 2; ni++)
                wmma::load_matrix_sync(bf[ni], &Bs[wn * 32 + ni * 16][kf * 8], 36);
            #pragma unroll
            for (int mi = 0; mi < 4; mi++)
                #pragma unroll
                for (int ni = 0; ni < 2; ni++)
                    wmma::mma_sync(c[mi][ni], af[mi], bf[ni], c[mi][ni]);
        }
        __syncthreads();
    }
    #pragma unroll
    for (int mi = 0; mi < 4; mi++) {
        int r0 = wm * 64 + mi * 16;       // consecutive 16 rows, same b
        int b = r0 >> 4;
        float* dst = &g_S[(size_t)((b * 8 + h) * 16) * 4096 + n0 + wn * 32];
        #pragma unroll
        for (int ni = 0; ni < 2; ni++)
            wmma::store_matrix_sync(dst + ni * 16, c[mi][ni], 4096, wmma::mem_row_major);
    }
}

// ---------------- K5: scores (tf32 TC, rinv fused): S += tq' @ (X*rinv) ------------
__global__ void __launch_bounds__(256) k_scores_tc(const float* __restrict__ X) {
    __shared__ __align__(16) float As[128][36];
    __shared__ __align__(16) float Bs[32][132];
    __shared__ __align__(16) float rs[128];
    __shared__ float ss2[256];
    int n0 = blockIdx.x * 128, b = blockIdx.y, t = threadIdx.x;
    int w = t >> 5, wm = w >> 2, wn = w & 3;
    const float* Xb = X + (size_t)b * CC * NN;
    const float* TQ = g_TQ + (size_t)b * 128 * 256;
    float* Sb = g_S + (size_t)b * 128 * 4096;
    {
        int tn = t & 127, chh = t >> 7;
        const float* xp = Xb + (size_t)(chh * 128) * 4096 + n0 + tn;
        float s0 = 0.f, s1 = 0.f, s2 = 0.f, s3 = 0.f;
        #pragma unroll 4
        for (int c = 0; c < 128; c += 4) {
            float v0 = xp[(size_t)(c + 0) * 4096];
            float v1 = xp[(size_t)(c + 1) * 4096];
            float v2 = xp[(size_t)(c + 2) * 4096];
            float v3 = xp[(size_t)(c + 3) * 4096];
            s0 += v0 * v0; s1 += v1 * v1; s2 += v2 * v2; s3 += v3 * v3;
        }
        ss2[t] = (s0 + s1) + (s2 + s3);
    }
    __syncthreads();
    if (t < 128) {
        float rv = rsqrtf((ss2[t] + ss2[t + 128]) * (1.0f / 256.0f) + EPSV);
        rs[t] = rv;
        g_RINV[b * 4096 + n0 + t] = rv;
    }
    __syncthreads();
    wmma::fragment<wmma::accumulator, 16, 16, 8, float> c[4][2];
    #pragma unroll
    for (int mi = 0; mi < 4; mi++)
        #pragma unroll
        for (int ni = 0; ni < 2; ni++)
            wmma::load_matrix_sync(c[mi][ni],
                &Sb[(size_t)(wm * 64 + mi * 16) * 4096 + n0 + wn * 32 + ni * 16],
                4096, wmma::mem_row_major);
    for (int c0 = 0; c0 < 256; c0 += 32) {
        #pragma unroll
        for (int r = 0; r < 4; r++) {
            int i = t + 256 * r, row = i >> 3, kq = i & 7;
            float4 v = *(const float4*)&TQ[(size_t)row * 256 + c0 + kq * 4];
            As[row][kq * 4 + 0] = wmma::__float_to_tf32(v.x);
            As[row][kq * 4 + 1] = wmma::__float_to_tf32(v.y);
            As[row][kq * 4 + 2] = wmma::__float_to_tf32(v.z);
            As[row][kq * 4 + 3] = wmma::__float_to_tf32(v.w);
        }
        #pragma unroll
        for (int r = 0; r < 4; r++) {
            int i = t + 256 * r, kk = i >> 5, nq = i & 31;
            float4 v = *(const float4*)&Xb[(size_t)(c0 + kk) * 4096 + n0 + nq * 4];
            Bs[kk][nq * 4 + 0] = wmma::__float_to_tf32(v.x * rs[nq * 4 + 0]);
            Bs[kk][nq * 4 + 1] = wmma::__float_to_tf32(v.y * rs[nq * 4 + 1]);
            Bs[kk][nq * 4 + 2] = wmma::__float_to_tf32(v.z * rs[nq * 4 + 2]);
            Bs[kk][nq * 4 + 3] = wmma::__float_to_tf32(v.w * rs[nq * 4 + 3]);
        }
        __syncthreads();
        #pragma unroll
        for (int kf = 0; kf < 4; kf++) {
            wmma::fragment<wmma::matrix_a, 16, 16, 8, wmma::precision::tf32, wmma::row_major> af[4];
            wmma::fragment<wmma::matrix_b, 16, 16, 8, wmma::precision::tf32, wmma::row_major> bf[2];
            #pragma unroll
            for (int mi = 0; mi < 4; mi++)
                wmma::load_matrix_sync(af[mi], &As[wm * 64 + mi * 16][kf * 8], 36);
            #pragma unroll
            for (int ni = 0; ni < 2; ni++)
                wmma::load_matrix_sync(bf[ni], &Bs[kf * 8][wn * 32 + ni * 16], 132);
            #pragma unroll
            for (int mi = 0; mi < 4; mi++)
                #pragma unroll
                for (int ni = 0; ni < 2; ni++)
                    wmma::mma_sync(c[mi][ni], af[mi], bf[ni], c[mi][ni]);
        }
        __syncthreads();
    }
    #pragma unroll
    for (int mi = 0; mi < 4; mi++)
        #pragma unroll
        for (int ni = 0; ni < 2; ni++)
            wmma::store_matrix_sync(&Sb[(size_t)(wm * 64 + mi * 16) * 4096 + n0 + wn * 32 + ni * 16],
                                    c[mi][ni], 4096, wmma::mem_row_major);
}

// ---------------- K6: softmax over n=4096 (512 thr) --------------------------------
__global__ void k_softmax() {
    __shared__ float red[32];
    int row = blockIdx.x;
    float* s = g_S + (size_t)row * NN;
    int t = threadIdx.x;  // 512
    float loc[8];
    float m = -1e30f;
    #pragma unroll
    for (int i = 0; i < 8; i++) { loc[i] = s[t + i * 512]; m = fmaxf(m, loc[i]); }
    m = blk_red<16, true>(m, red);
    float sum = 0.0f;
    #pragma unroll
    for (int i = 0; i < 8; i++) { loc[i] = __expf(loc[i] - m); sum += loc[i]; }
    sum = blk_red<16, false>(sum, red);
    float inv = 1.0f / sum;
    #pragma unroll
    for (int i = 0; i < 8; i++) s[t + i * 512] = loc[i] * inv;
}

// ---------------- K7: pa partials (tf32 TC): (p*rinv) @ X^T ------------------------
__global__ void __launch_bounds__(512) k_pa_tc(const float* __restrict__ X) {
    __shared__ __align__(16) float As[128][20];
    __shared__ __align__(16) float Bs[256][20];
    int ks = blockIdx.x, b = blockIdx.y, t = threadIdx.x;
    int nbase = ks * 256;
    int w = t >> 5, wm = w >> 3, wn = w & 7;
    const float* Xb = X + (size_t)b * CC * NN;
    wmma::fragment<wmma::accumulator, 16, 16, 8, float> c[4][2];
    #pragma unroll
    for (int mi = 0; mi < 4; mi++)
        #pragma unroll
        for (int ni = 0; ni < 2; ni++) wmma::fill_fragment(c[mi][ni], 0.0f);
    for (int k0 = 0; k0 < 256; k0 += 16) {
        {
            int row = t >> 2, kq = t & 3;
            int n = nbase + k0 + kq * 4;
            float4 p  = *(const float4*)&g_S[(size_t)(b * 128 + row) * 4096 + n];
            float4 rv = *(const float4*)&g_RINV[b * 4096 + n];
            As[row][kq * 4 + 0] = wmma::__float_to_tf32(p.x * rv.x);
            As[row][kq * 4 + 1] = wmma::__float_to_tf32(p.y * rv.y);
            As[row][kq * 4 + 2] = wmma::__float_to_tf32(p.z * rv.z);
            As[row][kq * 4 + 3] = wmma::__float_to_tf32(p.w * rv.w);
        }
        #pragma unroll
        for (int r = 0; r < 2; r++) {
            int i = t + 512 * r, cc = i >> 2, kq = i & 3;
            float4 v = *(const float4*)&Xb[(size_t)cc * 4096 + nbase + k0 + kq * 4];
            Bs[cc][kq * 4 + 0] = wmma::__float_to_tf32(v.x);
            Bs[cc][kq * 4 + 1] = wmma::__float_to_tf32(v.y);
            Bs[cc][kq * 4 + 2] = wmma::__float_to_tf32(v.z);
            Bs[cc][kq * 4 + 3] = wmma::__float_to_tf32(v.w);
        }
        __syncthreads();
        #pragma unroll
        for (int kf = 0; kf < 2; kf++) {
            wmma::fragment<wmma::matrix_a, 16, 16, 8, wmma::precision::tf32, wmma::row_major> af[4];
            wmma::fragment<wmma::matrix_b, 16, 16, 8, wmma::precision::tf32, wmma::col_major> bf[2];
            #pragma unroll
            for (int mi = 0; mi < 4; mi++)
                wmma::load_matrix_sync(af[mi], &As[wm * 64 + mi * 16][kf * 8], 20);
            #pragma unroll
            for (int ni = 0; ni < 2; ni++)
                wmma::load_matrix_sync(bf[ni], &Bs[wn * 32 + ni * 16][kf * 8], 20);
            #pragma unroll
            for (int mi = 0; mi < 4; mi++)
                #pragma unroll
                for (int ni = 0; ni < 2; ni++)
                    wmma::mma_sync(c[mi][ni], af[mi], bf[ni], c[mi][ni]);
        }
        __syncthreads();
    }
    #pragma unroll
    for (int mi = 0; mi < 4; mi++)
        #pragma unroll
        for (int ni = 0; ni < 2; ni++)
            wmma::store_matrix_sync(
                &g_PAP[(size_t)((ks * 8 + b) * 128 + wm * 64 + mi * 16) * 256 + wn * 32 + ni * 16],
                c[mi][ni], 256, wmma::mem_row_major);
}

// ---------------- K8: ope partials (tf32 TC): p @ (PE_h + bv + b2) ----------------
__global__ void __launch_bounds__(256) k_ppe_tc(const float* __restrict__ bkv,
                                                const float* __restrict__ peb2) {
    __shared__ __align__(16) float As[128][36];
    __shared__ __align__(16) float Bs[32][68];
    __shared__ float bias_s[64];
    int h = blockIdx.x, ks = blockIdx.y, t = threadIdx.x;
    int nb = ks * 512;
    int w = t >> 5, wm = w >> 1, wn = w & 1;
    if (t < 16) {
        float4 bv4 = *(const float4*)&bkv[512 + h * 64 + t * 4];
        float4 b24 = *(const float4*)&peb2[h * 64 + t * 4];
        bias_s[t * 4 + 0] = bv4.x + b24.x;
        bias_s[t * 4 + 1] = bv4.y + b24.y;
        bias_s[t * 4 + 2] = bv4.z + b24.z;
        bias_s[t * 4 + 3] = bv4.w + b24.w;
    }
    __syncthreads();
    wmma::fragment<wmma::accumulator, 16, 16, 8, float> c[2][2];
    #pragma unroll
    for (int mi = 0; mi < 2; mi++)
        #pragma unroll
        for (int ni = 0; ni < 2; ni++) wmma::fill_fragment(c[mi][ni], 0.0f);
    for (int k0 = 0; k0 < 512; k0 += 32) {
        #pragma unroll
        for (int r = 0; r < 4; r++) {
            int i = t + 256 * r, row = i >> 3, kq = i & 7;
            int b = row >> 4, e = row & 15;
            float4 v = *(const float4*)&g_S[(size_t)((b * 8 + h) * 16 + e) * 4096 + nb + k0 + kq * 4];
            As[row][kq * 4 + 0] = wmma::__float_to_tf32(v.x);
            As[row][kq * 4 + 1] = wmma::__float_to_tf32(v.y);
            As[row][kq * 4 + 2] = wmma::__float_to_tf32(v.z);
            As[row][kq * 4 + 3] = wmma::__float_to_tf32(v.w);
        }
        #pragma unroll
        for (int r = 0; r < 2; r++) {
            int i = t + 256 * r, kk = i >> 4, dq = i & 15;
            float4 v = *(const float4*)&g_PE[(size_t)(nb + k0 + kk) * 512 + h * 64 + dq * 4];
            Bs[kk][dq * 4 + 0] = wmma::__float_to_tf32(v.x + bias_s[dq * 4 + 0]);
            Bs[kk][dq * 4 + 1] = wmma::__float_to_tf32(v.y + bias_s[dq * 4 + 1]);
            Bs[kk][dq * 4 + 2] = wmma::__float_to_tf32(v.z + bias_s[dq * 4 + 2]);
            Bs[kk][dq * 4 + 3] = wmma::__float_to_tf32(v.w + bias_s[dq * 4 + 3]);
        }
        __syncthreads();
        #pragma unroll
        for (int kf = 0; kf < 4; kf++) {
            wmma::fragment<wmma::matrix_a, 16, 16, 8, wmma::precision::tf32, wmma::row_major> af[2];
            wmma::fragment<wmma::matrix_b, 16, 16, 8, wmma::precision::tf32, wmma::row_major> bf[2];
            #pragma unroll
            for (int mi = 0; mi < 2; mi++)
                wmma::load_matrix_sync(af[mi], &As[wm * 32 + mi * 16][kf * 8], 36);
            #pragma unroll
            for (int ni = 0; ni < 2; ni++)
                wmma::load_matrix_sync(bf[ni], &Bs[kf * 8][wn * 32 + ni * 16], 68);
            #pragma unroll
            for (int mi = 0; mi < 2; mi++)
                #pragma unroll
                for (int ni = 0; ni < 2; ni++)
                    wmma::mma_sync(c[mi][ni], af[mi], bf[ni], c[mi][ni]);
        }
        __syncthreads();
    }
    #pragma unroll
    for (int mi = 0; mi < 2; mi++)
        #pragma unroll
        for (int ni = 0; ni < 2; ni++)
            wmma::store_matrix_sync(
                &g_OPEP[(size_t)((ks * 8 + h) * 128 + wm * 32 + mi * 16) * 64 + wn * 32 + ni * 16],
                c[mi][ni], 64, wmma::mem_row_major);
}

// ---------------- K9: out0 = (pa*wp-reduced) @ Wv + ope ---------------------------
__global__ void __launch_bounds__(512) k_out(const float* __restrict__ wkv,
                                             const float* __restrict__ wp) {
    __shared__ float pool[8192];
    __shared__ float ope_s[4][512];
    int row0 = blockIdx.x * 4;
    int t = threadIdx.x;
    for (int idx = t; idx < 8192; idx += 512) {
        int r = idx >> 11, rest = idx & 2047, h = rest >> 8, c = rest & 255;
        int row = row0 + r, b = row >> 4, e = row & 15;
        float s = 0.f;
        #pragma unroll
        for (int ks = 0; ks < 16; ks++)
            s += g_PAP[(size_t)((ks * 8 + b) * 128 + h * 16 + e) * 256 + c];
        pool[idx] = s * wp[c];
    }
    for (int idx = t; idx < 2048; idx += 512) {
        int r = idx >> 9, j = idx & 511;
        int row = row0 + r, b = row >> 4, e = row & 15;
        int h = j >> 6, d = j & 63;
        float s = 0.f;
        #pragma unroll
        for (int ks = 0; ks < 8; ks++)
            s += g_OPEP[(size_t)((ks * 8 + h) * 128 + b * 16 + e) * 64 + d];
        ope_s[r][j] = s;
    }
    __syncthreads();
    int tj = t & 127, tk = t >> 7;
    int h = tj >> 4;
    float4 acc[4];
    #pragma unroll
    for (int r = 0; r < 4; r++) acc[r] = make_float4(0.f, 0.f, 0.f, 0.f);
    #pragma unroll 4
    for (int c = tk * 64; c < tk * 64 + 64; c++) {
        float4 w4 = *(const float4*)&wkv[(size_t)c * 1024 + 512 + tj * 4];
        #pragma unroll
        for (int r = 0; r < 4; r++) {
            float p = pool[r * 2048 + h * 256 + c];
            acc[r].x += p * w4.x; acc[r].y += p * w4.y;
            acc[r].z += p * w4.z; acc[r].w += p * w4.w;
        }
    }
    __syncthreads();
    #pragma unroll
    for (int r = 0; r < 4; r++) *(float4*)&pool[(tk * 4 + r) * 512 + tj * 4] = acc[r];
    __syncthreads();
    {
        int r = t >> 7, j0 = (t & 127) * 4;
        float4 s = make_float4(0.f, 0.f, 0.f, 0.f);
        #pragma unroll
        for (int k2 = 0; k2 < 4; k2++) {
            float4 p = *(const float4*)&pool[(k2 * 4 + r) * 512 + j0];
            s.x += p.x; s.y += p.y; s.z += p.z; s.w += p.w;
        }
        float4 op = *(const float4*)&ope_s[r][j0];
        s.x += op.x; s.y += op.y; s.z += op.z; s.w += op.w;
        *(float4*)&g_ATT0[(row0 + r) * 512 + j0] = s;
    }
}

// ---------------- K10: proj + residual ---------------------------------------------
__global__ void __launch_bounds__(256) k_proj(const float* __restrict__ wproj,
                                              const float* __restrict__ bproj) {
    __shared__ float x_s[8][512];
    __shared__ float part[8][8][128];
    int row0 = blockIdx.x * 8, jb = blockIdx.y * 128, t = threadIdx.x;
    for (int idx = t; idx < 4096; idx += 256)
        x_s[idx >> 9][idx & 511] = g_ATT0[(row0 + (idx >> 9)) * 512 + (idx & 511)];
    __syncthreads();
    int tk = t >> 5, tj = t & 31, j = jb + tj * 4;
    float4 acc[8];
    #pragma unroll
    for (int r = 0; r < 8; r++) acc[r] = make_float4(0.f, 0.f, 0.f, 0.f);
    #pragma unroll 8
    for (int c = tk * 64; c < tk * 64 + 64; c++) {
        float4 w4 = *(const float4*)&wproj[(size_t)c * 512 + j];
        #pragma unroll
        for (int r = 0; r < 8; r++) {
            float x = x_s[r][c];
            acc[r].x += x * w4.x; acc[r].y += x * w4.y;
            acc[r].z += x * w4.z; acc[r].w += x * w4.w;
        }
    }
    #pragma unroll
    for (int r = 0; r < 8; r++) *(float4*)&part[tk][r][tj * 4] = acc[r];
    __syncthreads();
    {
        int r = t >> 5, cq = t & 31, j2 = jb + cq * 4;
        float4 s = make_float4(0.f, 0.f, 0.f, 0.f);
        #pragma unroll
        for (int k2 = 0; k2 < 8; k2++) {
            float4 p = *(const float4*)&part[k2][r][cq * 4];
            s.x += p.x; s.y += p.y; s.z += p.z; s.w += p.w;
        }
        float4 bp = *(const float4*)&bproj[j2];
        float4 mn = *(const float4*)&g_MOLN[(row0 + r) * 512 + j2];
        s.x += bp.x + mn.x; s.y += bp.y + mn.y;
        s.z += bp.z + mn.z; s.w += bp.w + mn.w;
        *(float4*)&g_ATT[(row0 + r) * 512 + j2] = s;
    }
}

// ---------------- K11: ffn1 (fused rmsnorm) + gelu ----------------------------------
__global__ void __launch_bounds__(256) k_ffn1(const float* __restrict__ nw,
                                              const float* __restrict__ w1,
                                              const float* __restrict__ b1) {
    __shared__ float x_s[8][512];
    __shared__ float part[8][8][128];
    int row0 = blockIdx.x * 8, jb = blockIdx.y * 128, t = threadIdx.x;
    int w = t >> 5, lane = t & 31;
    {
        float vals[16]; float ss = 0.f;
        #pragma unroll
        for (int i = 0; i < 16; i++) {
            float v = g_ATT[(row0 + w) * 512 + lane + i * 32];
            vals[i] = v; ss += v * v;
        }
        #pragma unroll
        for (int o = 16; o; o >>= 1) ss += __shfl_xor_sync(0xffffffffu, ss, o);
        float rv = rsqrtf(ss * (1.0f / 512.0f) + EPSV);
        #pragma unroll
        for (int i = 0; i < 16; i++) {
            int m = lane + i * 32;
            x_s[w][m] = vals[i] * rv * nw[m];
        }
    }
    __syncthreads();
    int tk = t >> 5, tj = t & 31, j = jb + tj * 4;
    float4 acc[8];
    #pragma unroll
    for (int r = 0; r < 8; r++) acc[r] = make_float4(0.f, 0.f, 0.f, 0.f);
    #pragma unroll 8
    for (int c = tk * 64; c < tk * 64 + 64; c++) {
        float4 w4 = *(const float4*)&w1[(size_t)c * 2048 + j];
        #pragma unroll
        for (int r = 0; r < 8; r++) {
            float x = x_s[r][c];
            acc[r].x += x * w4.x; acc[r].y += x * w4.y;
            acc[r].z += x * w4.z; acc[r].w += x * w4.w;
        }
    }
    #pragma unroll
    for (int r = 0; r < 8; r++) *(float4*)&part[tk][r][tj * 4] = acc[r];
    __syncthreads();
    {
        int r = t >> 5, cq = t & 31, j2 = jb + cq * 4;
        float4 s = make_float4(0.f, 0.f, 0.f, 0.f);
        #pragma unroll
        for (int k2 = 0; k2 < 8; k2++) {
            float4 p = *(const float4*)&part[k2][r][cq * 4];
            s.x += p.x; s.y += p.y; s.z += p.z; s.w += p.w;
        }
        float4 bb = *(const float4*)&b1[j2];
        float4 o;
        o.x = geluf(s.x + bb.x); o.y = geluf(s.y + bb.y);
        o.z = geluf(s.z + bb.z); o.w = geluf(s.w + bb.w);
        *(float4*)&g_H1[(size_t)(row0 + r) * 2048 + j2] = o;
    }
}

// ---------------- K12: ffn2 + residual ----------------------------------------------
__global__ void __launch_bounds__(512) k_ffn2(const float* __restrict__ w2,
                                              const float* __restrict__ b2,
                                              float* __restrict__ out) {
    __shared__ float pool[8192];
    int row0 = blockIdx.x * 4, jb = blockIdx.y * 128, t = threadIdx.x;
    for (int idx = t; idx < 8192; idx += 512)
        pool[idx] = g_H1[(size_t)(row0 + (idx >> 11)) * 2048 + (idx & 2047)];
    __syncthreads();
    int tk = t >> 5, tj = t & 31, j = jb + tj * 4;
    float4 acc[4];
    #pragma unroll
    for (int r = 0; r < 4; r++) acc[r] = make_float4(0.f, 0.f, 0.f, 0.f);
    #pragma unroll 8
    for (int c = tk * 128; c < tk * 128 + 128; c++) {
        float4 w4 = *(const float4*)&w2[(size_t)c * 512 + j];
        #pragma unroll
        for (int r = 0; r < 4; r++) {
            float x = pool[r * 2048 + c];
            acc[r].x += x * w4.x; acc[r].y += x * w4.y;
            acc[r].z += x * w4.z; acc[r].w += x * w4.w;
        }
    }
    __syncthreads();
    #pragma unroll
    for (int r = 0; r < 4; r++) *(float4*)&pool[tk * 512 + r * 128 + tj * 4] = acc[r];
    __syncthreads();
    {
        int r = t >> 7, cq = t & 127;
        float s = 0.f;
        #pragma unroll
        for (int k2 = 0; k2 < 16; k2++) s += pool[k2 * 512 + r * 128 + cq];
        int j2 = jb + cq;
        out[(row0 + r) * 512 + j2] = s + b2[j2] + g_ATT[(row0 + r) * 512 + j2];
    }
}

// ---------------- launch -------------------------------------------------------------
extern "C" void kernel_launch(void* const* d_in, const int* in_sizes, int n_in,
                              void* d_out, int out_size) {
    const float* patch   = (const float*)d_in[0];
    const float* mol     = (const float*)d_in[1];
    const float* pe_w1   = (const float*)d_in[2];
    const float* pe_b1   = (const float*)d_in[3];
    const float* pe_w2   = (const float*)d_in[4];
    const float* pe_b2   = (const float*)d_in[5];
    const float* wq      = (const float*)d_in[6];
    const float* bq      = (const float*)d_in[7];
    const float* wkv     = (const float*)d_in[8];
    const float* bkv     = (const float*)d_in[9];
    const float* wproj   = (const float*)d_in[10];
    const float* bproj   = (const float*)d_in[11];
    const float* nmolw   = (const float*)d_in[12];
    const float* npatchw = (const float*)d_in[13];
    const float* ffn_w1  = (const float*)d_in[14];
    const float* ffn_b1  = (const float*)d_in[15];
    const float* ffn_w2  = (const float*)d_in[16];
    const float* ffn_b2  = (const float*)d_in[17];
    const float* ffn_nw  = (const float*)d_in[18];
    float* out = (float*)d_out;
    (void)in_sizes; (void)n_in; (void)out_size;

    k_peg_tc   <<<dim3(32, 4), 256>>>(pe_w1, pe_b1, pe_w2);
    k_molq     <<<dim3(16, 4), 256>>>(mol, nmolw, wq, bq);
    k_tq2      <<<dim3(8, 2), 256>>>(wkv, npatchw);
    k_qpe_tc   <<<dim3(32, 8), 256>>>();
    k_scores_tc<<<dim3(32, 8), 256>>>(patch);
    k_softmax  <<<BB * 128, 512>>>();
    k_pa_tc    <<<dim3(16, 8), 512>>>(patch);
    k_ppe_tc   <<<dim3(8, 8), 256>>>(bkv, pe_b2);
    k_out      <<<32, 512>>>(wkv, npatchw);
    k_proj     <<<dim3(16, 4), 256>>>(wproj, bproj);
    k_ffn1     <<<dim3(16, 16), 256>>>(ffn_nw, ffn_w1, ffn_b1);
    k_ffn2     <<<dim3(32, 4), 512>>>(ffn_w2, ffn_b2, out);
}